// round 10
// baseline (speedup 1.0000x reference)
#include <cuda_runtime.h>
#include <cuda_fp16.h>
#include <stdint.h>

// Problem constants
#define CB 2
#define CL 2048
#define CD 1024
#define CH 16
#define CDK 64

constexpr int  BHn        = CB * CH;               // 32
constexpr long PROJ_ELEMS = (long)CB * CL * CD;    // 4,194,304
constexpr long ZN         = (long)BHn * CL;        // 65,536

// Scratch (static device globals -- no runtime allocation)
__device__ __half  g_Qh[PROJ_ELEMS];               // Q proj -> normalized, fp16
__device__ __half  g_Kh[PROJ_ELEMS];               // K proj -> normalized, fp16
__device__ __half  g_Vh[PROJ_ELEMS];               // V projection, fp16
__device__ float   g_invZ[ZN];

// ---------------------------------------------------------------------------
// helpers
// ---------------------------------------------------------------------------
__device__ __forceinline__ void mma16h(float* d, const uint32_t* a, const uint32_t* b) {
    asm volatile(
        "mma.sync.aligned.m16n8k16.row.col.f32.f16.f16.f32 "
        "{%0,%1,%2,%3}, {%4,%5,%6,%7}, {%8,%9}, {%0,%1,%2,%3};"
        : "+f"(d[0]), "+f"(d[1]), "+f"(d[2]), "+f"(d[3])
        : "r"(a[0]), "r"(a[1]), "r"(a[2]), "r"(a[3]), "r"(b[0]), "r"(b[1]));
}

__device__ __forceinline__ uint32_t sptr(const void* p) {
    return (uint32_t)__cvta_generic_to_shared(p);
}

__device__ __forceinline__ void ldm4(uint32_t* a, uint32_t addr) {
    asm volatile("ldmatrix.sync.aligned.m8n8.x4.shared.b16 {%0,%1,%2,%3}, [%4];"
                 : "=r"(a[0]), "=r"(a[1]), "=r"(a[2]), "=r"(a[3]) : "r"(addr));
}

__device__ __forceinline__ void ldm4t(uint32_t* a, uint32_t addr) {
    asm volatile("ldmatrix.sync.aligned.m8n8.x4.trans.shared.b16 {%0,%1,%2,%3}, [%4];"
                 : "=r"(a[0]), "=r"(a[1]), "=r"(a[2]), "=r"(a[3]) : "r"(addr));
}

// ---------------------------------------------------------------------------
// fp16-MMA NT projection GEMM: C[m,n] = half( sum_k A[m,k]*B[n,k] )
// BM=64, BN=128, BK=32, 256 threads (2x4 warps), ldmatrix, fp32 accum.
// ---------------------------------------------------------------------------
__global__ __launch_bounds__(256) void proj_h_kernel(
    const float* __restrict__ A, const float* __restrict__ B,
    __half* __restrict__ C)
{
    __shared__ __half As[64][40];
    __shared__ __half Bs[128][40];

    const float* Ab = A + (long)blockIdx.y * 64 * CD;
    const float* Bb = B + (long)blockIdx.x * 128 * CD;

    const int tid  = threadIdx.x;
    const int w    = tid >> 5, lane = tid & 31;
    const int wm   = w >> 2, wn = w & 3;
    const int g    = lane >> 2, tig = lane & 3;

    float acc[2][4][4];
    #pragma unroll
    for (int i = 0; i < 2; i++)
        #pragma unroll
        for (int j = 0; j < 4; j++)
            #pragma unroll
            for (int r = 0; r < 4; r++) acc[i][j][r] = 0.f;

    float4 pa[2], pb[4];
    #pragma unroll
    for (int j = 0; j < 2; j++) {
        int s = tid + 256 * j;
        pa[j] = *(const float4*)(Ab + (long)(s >> 3) * CD + (s & 7) * 4);
    }
    #pragma unroll
    for (int j = 0; j < 4; j++) {
        int s = tid + 256 * j;
        pb[j] = *(const float4*)(Bb + (long)(s >> 3) * CD + (s & 7) * 4);
    }

    for (int k0 = 0; k0 < CD; k0 += 32) {
        #pragma unroll
        for (int j = 0; j < 2; j++) {
            int s = tid + 256 * j;
            int r = s >> 3, c = (s & 7) * 4;
            As[r][c + 0] = __float2half(pa[j].x);
            As[r][c + 1] = __float2half(pa[j].y);
            As[r][c + 2] = __float2half(pa[j].z);
            As[r][c + 3] = __float2half(pa[j].w);
        }
        #pragma unroll
        for (int j = 0; j < 4; j++) {
            int s = tid + 256 * j;
            int r = s >> 3, c = (s & 7) * 4;
            Bs[r][c + 0] = __float2half(pb[j].x);
            Bs[r][c + 1] = __float2half(pb[j].y);
            Bs[r][c + 2] = __float2half(pb[j].z);
            Bs[r][c + 3] = __float2half(pb[j].w);
        }
        __syncthreads();

        if (k0 + 32 < CD) {
            #pragma unroll
            for (int j = 0; j < 2; j++) {
                int s = tid + 256 * j;
                pa[j] = *(const float4*)(Ab + (long)(s >> 3) * CD + k0 + 32 + (s & 7) * 4);
            }
            #pragma unroll
            for (int j = 0; j < 4; j++) {
                int s = tid + 256 * j;
                pb[j] = *(const float4*)(Bb + (long)(s >> 3) * CD + k0 + 32 + (s & 7) * 4);
            }
        }

        #pragma unroll
        for (int ks = 0; ks < 2; ks++) {
            const int c0 = ks * 16;
            uint32_t af[2][4], bf[4][2];
            #pragma unroll
            for (int mt = 0; mt < 2; mt++)
                ldm4(af[mt], sptr(&As[wm * 32 + mt * 16 + (lane & 15)][c0 + (lane >> 4) * 8]));
            #pragma unroll
            for (int nh = 0; nh < 2; nh++) {
                uint32_t r4[4];
                ldm4(r4, sptr(&Bs[wn * 32 + nh * 16 + (lane & 15)][c0 + (lane >> 4) * 8]));
                bf[2 * nh][0]     = r4[0]; bf[2 * nh][1]     = r4[2];
                bf[2 * nh + 1][0] = r4[1]; bf[2 * nh + 1][1] = r4[3];
            }
            #pragma unroll
            for (int mt = 0; mt < 2; mt++)
                #pragma unroll
                for (int nt = 0; nt < 4; nt++)
                    mma16h(acc[mt][nt], af[mt], bf[nt]);
        }
        __syncthreads();
    }

    __half* Cb = C + (long)blockIdx.y * 64 * CD + (long)blockIdx.x * 128;
    #pragma unroll
    for (int mt = 0; mt < 2; mt++)
        #pragma unroll
        for (int nt = 0; nt < 4; nt++) {
            long r0  = wm * 32 + mt * 16 + g;
            int  col = wn * 32 + nt * 8 + 2 * tig;
            *(__half2*)&Cb[r0 * CD + col] =
                __floats2half2_rn(acc[mt][nt][0], acc[mt][nt][1]);
            *(__half2*)&Cb[(r0 + 8) * CD + col] =
                __floats2half2_rn(acc[mt][nt][2], acc[mt][nt][3]);
        }
}

// ---------------------------------------------------------------------------
// In-place L2 normalize of each 64-half segment; one warp per segment.
// blockIdx.y selects tensor: 0 -> Q (coef 0.125), 1 -> K (coef 1).
// ---------------------------------------------------------------------------
__global__ __launch_bounds__(256) void l2norm_h_kernel(__half* __restrict__ Q,
                                                       __half* __restrict__ K)
{
    __half* X = blockIdx.y ? K : Q;
    const float coef = blockIdx.y ? 1.0f : 0.125f;
    const int seg  = blockIdx.x * 8 + (threadIdx.x >> 5);
    const int lane = threadIdx.x & 31;
    __half2* p = (__half2*)(X + (long)seg * 64) + lane;
    float2 u = __half22float2(*p);
    float ss = u.x * u.x + u.y * u.y;
    #pragma unroll
    for (int o = 16; o; o >>= 1) ss += __shfl_xor_sync(0xffffffffu, ss, o);
    const float s = coef / fmaxf(sqrtf(ss), 1e-12f);
    *p = __floats2half2_rn(u.x * s, u.y * s);
}

// ---------------------------------------------------------------------------
// Fused flash attention (no-max softmax; scores bounded by 1/8):
// per (b,h,128-q tile): loop 64-k tiles: S=Q.K^T (fp16 MMA), E=exp(S) kept
// in registers only -> O += E.V (fp16 MMA), Z += rowsum(E).
// Epilogue: out = O/Z; invZ stored for the avg recompute pass.
// 256 threads = 8 warps, each warp owns 16 q rows.  grid (CL/128, BHn).
// ---------------------------------------------------------------------------
__global__ __launch_bounds__(256) void flash_kernel(
    const __half* __restrict__ Qh, const __half* __restrict__ Kh,
    const __half* __restrict__ Vh,
    float* __restrict__ invZ, float* __restrict__ out)
{
    __shared__ __half Qs[128][72];
    __shared__ __half Ks[64][72];
    __shared__ __half Vs[64][72];

    const int z = blockIdx.y, b = z >> 4, h = z & 15;
    const int qbase = blockIdx.x * 128;
    const int tid = threadIdx.x, w = tid >> 5, lane = tid & 31;
    const int g = lane >> 2, tig = lane & 3;

    // stage Q tile, pull per-warp A fragments (held for the whole kernel)
    const __half* Qg = Qh + ((long)b * CL + qbase) * CD + h * 64;
    #pragma unroll
    for (int j = 0; j < 4; j++) {
        int f = tid + 256 * j;
        int r = f >> 3, c = (f & 7) * 8;
        *(uint4*)&Qs[r][c] = *(const uint4*)(Qg + (long)r * CD + c);
    }
    __syncthreads();
    uint32_t aq[4][4];
    #pragma unroll
    for (int kc = 0; kc < 4; kc++)
        ldm4(aq[kc], sptr(&Qs[w * 16 + (lane & 15)][kc * 16 + (lane >> 4) * 8]));

    const __half* Kg = Kh + (long)b * CL * CD + h * 64;
    const __half* Vg = Vh + (long)b * CL * CD + h * 64;

    float acc_o[8][4];
    #pragma unroll
    for (int i = 0; i < 8; i++)
        #pragma unroll
        for (int r = 0; r < 4; r++) acc_o[i][r] = 0.f;
    float zr0 = 0.f, zr1 = 0.f;

    uint4 pk[2], pv[2];
    #pragma unroll
    for (int j = 0; j < 2; j++) {
        int f = tid + 256 * j;
        int r = f >> 3, c = (f & 7) * 8;
        pk[j] = *(const uint4*)(Kg + (long)r * CD + c);
        pv[j] = *(const uint4*)(Vg + (long)r * CD + c);
    }

    for (int kt = 0; kt < CL / 64; kt++) {
        #pragma unroll
        for (int j = 0; j < 2; j++) {
            int f = tid + 256 * j;
            int r = f >> 3, c = (f & 7) * 8;
            *(uint4*)&Ks[r][c] = pk[j];
            *(uint4*)&Vs[r][c] = pv[j];
        }
        __syncthreads();

        if (kt + 1 < CL / 64) {
            #pragma unroll
            for (int j = 0; j < 2; j++) {
                int f = tid + 256 * j;
                int r = f >> 3, c = (f & 7) * 8;
                long row = (long)((kt + 1) * 64 + r);
                pk[j] = *(const uint4*)(Kg + row * CD + c);
                pv[j] = *(const uint4*)(Vg + row * CD + c);
            }
        }

        // scores: S[16q x 64k] per warp
        float s[8][4];
        #pragma unroll
        for (int i = 0; i < 8; i++)
            #pragma unroll
            for (int r = 0; r < 4; r++) s[i][r] = 0.f;

        #pragma unroll
        for (int kc = 0; kc < 4; kc++) {
            #pragma unroll
            for (int p = 0; p < 4; p++) {
                uint32_t r4[4];
                ldm4(r4, sptr(&Ks[p * 16 + (lane & 15)][kc * 16 + (lane >> 4) * 8]));
                uint32_t b0[2] = {r4[0], r4[2]}, b1[2] = {r4[1], r4[3]};
                mma16h(s[2 * p],     aq[kc], b0);
                mma16h(s[2 * p + 1], aq[kc], b1);
            }
        }

        // exp + fp16 repack (registers only) + row sums
        uint32_t ehlo[8], ehhi[8];
        #pragma unroll
        for (int nt = 0; nt < 8; nt++) {
            float e0 = __expf(s[nt][0]);
            float e1 = __expf(s[nt][1]);
            float e2 = __expf(s[nt][2]);
            float e3 = __expf(s[nt][3]);
            __half2 lo = __floats2half2_rn(e0, e1);
            __half2 hi = __floats2half2_rn(e2, e3);
            ehlo[nt] = *(uint32_t*)&lo;
            ehhi[nt] = *(uint32_t*)&hi;
            zr0 += e0 + e1;
            zr1 += e2 + e3;
        }

        // PV: O += E . V  (B via ldmatrix.trans on V[k][n])
        #pragma unroll
        for (int kc = 0; kc < 4; kc++) {
            uint32_t a[4] = {ehlo[2 * kc], ehhi[2 * kc], ehlo[2 * kc + 1], ehhi[2 * kc + 1]};
            #pragma unroll
            for (int p = 0; p < 4; p++) {
                uint32_t r4[4];
                ldm4t(r4, sptr(&Vs[kc * 16 + (lane & 15)][p * 16 + (lane >> 4) * 8]));
                uint32_t b0[2] = {r4[0], r4[1]}, b1[2] = {r4[2], r4[3]};
                mma16h(acc_o[2 * p],     a, b0);
                mma16h(acc_o[2 * p + 1], a, b1);
            }
        }
        __syncthreads();
    }

    // row sums across the 4 tig lanes (fixed order), then normalize + write
    zr0 += __shfl_xor_sync(0xffffffffu, zr0, 1);
    zr0 += __shfl_xor_sync(0xffffffffu, zr0, 2);
    zr1 += __shfl_xor_sync(0xffffffffu, zr1, 1);
    zr1 += __shfl_xor_sync(0xffffffffu, zr1, 2);
    const float iz0 = 1.0f / zr0;
    const float iz1 = 1.0f / zr1;
    if (tig == 0) {
        invZ[(long)z * CL + qbase + w * 16 + g]     = iz0;
        invZ[(long)z * CL + qbase + w * 16 + g + 8] = iz1;
    }
    float* Ob = out + (long)z * CL * CDK + (long)(qbase + w * 16) * CDK;
    #pragma unroll
    for (int nt = 0; nt < 8; nt++) {
        int col = nt * 8 + 2 * tig;
        *(float2*)&Ob[(long)g * CDK + col] =
            make_float2(acc_o[nt][0] * iz0, acc_o[nt][1] * iz0);
        *(float2*)&Ob[(long)(g + 8) * CDK + col] =
            make_float2(acc_o[nt][2] * iz1, acc_o[nt][3] * iz1);
    }
}

// ---------------------------------------------------------------------------
// avg recompute: per (b, qtile 128, ktile 128) CTA, loop over the 16 heads,
// recompute S = Q.K^T (fp16 MMA, identical fragments/order as flash), apply
// exp and invZ[h,q]/16 weights into persistent fp32 accumulators, write the
// avg tile once.  Q/K tiles are L2-resident (16 MB total).
// 256 threads = 8 warps; warp owns 16 q rows x 128 k cols.
// grid (CL/128, CL/128, CB).
// ---------------------------------------------------------------------------
__global__ __launch_bounds__(256) void avg_recompute_kernel(
    const __half* __restrict__ Qh, const __half* __restrict__ Kh,
    const float* __restrict__ invZ, float* __restrict__ avg)
{
    __shared__ __half Qs[128][72];
    __shared__ __half Ks[128][72];

    const int b = blockIdx.z;
    const int qbase = blockIdx.y * 128;
    const int kbase = blockIdx.x * 128;
    const int tid = threadIdx.x, w = tid >> 5, lane = tid & 31;
    const int g = lane >> 2, tig = lane & 3;

    float acc[16][4];
    #pragma unroll
    for (int i = 0; i < 16; i++)
        #pragma unroll
        for (int r = 0; r < 4; r++) acc[i][r] = 0.f;

    uint4 pq[4], pk[4];
    {
        const __half* Qg = Qh + ((long)b * CL + qbase) * CD;
        const __half* Kg = Kh + ((long)b * CL + kbase) * CD;
        #pragma unroll
        for (int j = 0; j < 4; j++) {
            int f = tid + 256 * j;
            int r = f >> 3, c = (f & 7) * 8;
            pq[j] = *(const uint4*)(Qg + (long)r * CD + c);
            pk[j] = *(const uint4*)(Kg + (long)r * CD + c);
        }
    }

    for (int h = 0; h < CH; h++) {
        #pragma unroll
        for (int j = 0; j < 4; j++) {
            int f = tid + 256 * j;
            int r = f >> 3, c = (f & 7) * 8;
            *(uint4*)&Qs[r][c] = pq[j];
            *(uint4*)&Ks[r][c] = pk[j];
        }
        __syncthreads();

        if (h + 1 < CH) {
            const __half* Qg = Qh + ((long)b * CL + qbase) * CD + (h + 1) * 64;
            const __half* Kg = Kh + ((long)b * CL + kbase) * CD + (h + 1) * 64;
            #pragma unroll
            for (int j = 0; j < 4; j++) {
                int f = tid + 256 * j;
                int r = f >> 3, c = (f & 7) * 8;
                pq[j] = *(const uint4*)(Qg + (long)r * CD + c);
                pk[j] = *(const uint4*)(Kg + (long)r * CD + c);
            }
        }

        uint32_t aq[4][4];
        #pragma unroll
        for (int kc = 0; kc < 4; kc++)
            ldm4(aq[kc], sptr(&Qs[w * 16 + (lane & 15)][kc * 16 + (lane >> 4) * 8]));

        const float w0 =
            invZ[(long)(b * CH + h) * CL + qbase + w * 16 + g] * (1.0f / CH);
        const float w1 =
            invZ[(long)(b * CH + h) * CL + qbase + w * 16 + g + 8] * (1.0f / CH);

        #pragma unroll
        for (int p = 0; p < 8; p++) {
            float s0[4] = {0.f, 0.f, 0.f, 0.f};
            float s1[4] = {0.f, 0.f, 0.f, 0.f};
            #pragma unroll
            for (int kc = 0; kc < 4; kc++) {
                uint32_t r4[4];
                ldm4(r4, sptr(&Ks[p * 16 + (lane & 15)][kc * 16 + (lane >> 4) * 8]));
                uint32_t b0[2] = {r4[0], r4[2]}, b1[2] = {r4[1], r4[3]};
                mma16h(s0, aq[kc], b0);
                mma16h(s1, aq[kc], b1);
            }
            acc[2 * p][0]     = fmaf(w0, __expf(s0[0]), acc[2 * p][0]);
            acc[2 * p][1]     = fmaf(w0, __expf(s0[1]), acc[2 * p][1]);
            acc[2 * p][2]     = fmaf(w1, __expf(s0[2]), acc[2 * p][2]);
            acc[2 * p][3]     = fmaf(w1, __expf(s0[3]), acc[2 * p][3]);
            acc[2 * p + 1][0] = fmaf(w0, __expf(s1[0]), acc[2 * p + 1][0]);
            acc[2 * p + 1][1] = fmaf(w0, __expf(s1[1]), acc[2 * p + 1][1]);
            acc[2 * p + 1][2] = fmaf(w1, __expf(s1[2]), acc[2 * p + 1][2]);
            acc[2 * p + 1][3] = fmaf(w1, __expf(s1[3]), acc[2 * p + 1][3]);
        }
        __syncthreads();
    }

    float* Ab = avg + ((long)b * CL + qbase + w * 16) * CL + kbase;
    #pragma unroll
    for (int nb = 0; nb < 16; nb++) {
        int col = nb * 8 + 2 * tig;
        *(float2*)&Ab[(long)g * CL + col]       = make_float2(acc[nb][0], acc[nb][1]);
        *(float2*)&Ab[(long)(g + 8) * CL + col] = make_float2(acc[nb][2], acc[nb][3]);
    }
}

// ---------------------------------------------------------------------------
extern "C" void kernel_launch(void* const* d_in, const int* in_sizes, int n_in,
                              void* d_out, int out_size)
{
    const float* q  = (const float*)d_in[0];
    const float* k  = (const float*)d_in[1];
    const float* v  = (const float*)d_in[2];
    const float* wq = (const float*)d_in[3];
    const float* wk = (const float*)d_in[4];
    const float* wv = (const float*)d_in[5];

    float* out = (float*)d_out;                        // [B,H,L,64]
    float* avg = out + (long)CB * CH * CL * CDK;       // [B,L,L]

    float  *iZ;
    __half *Qh, *Kh, *Vh;
    cudaGetSymbolAddress((void**)&Qh, g_Qh);
    cudaGetSymbolAddress((void**)&Kh, g_Kh);
    cudaGetSymbolAddress((void**)&Vh, g_Vh);
    cudaGetSymbolAddress((void**)&iZ, g_invZ);

    // 1) Projections (fp16 MMA, fp32 accumulate, fp16 out)
    dim3 pg(CD / 128, (CB * CL) / 64, 1);
    proj_h_kernel<<<pg, 256>>>(q, wq, Qh);
    proj_h_kernel<<<pg, 256>>>(k, wk, Kh);
    proj_h_kernel<<<pg, 256>>>(v, wv, Vh);

    // 2) In-place L2 normalize Q (fold 1/8) and K in one launch
    dim3 ng((CB * CL * CH) / 8, 2);
    l2norm_h_kernel<<<ng, 256>>>(Qh, Kh);

    // 3) Fused attention: out + invZ (no E materialization)
    dim3 fg(CL / 128, BHn);
    flash_kernel<<<fg, 256>>>(Qh, Kh, Vh, iZ, out);

    // 4) attn_avg by score recomputation
    dim3 ag(CL / 128, CL / 128, CB);
    avg_recompute_kernel<<<ag, 256>>>(Qh, Kh, iZ, avg);
}

// round 11
// speedup vs baseline: 1.1526x; 1.1526x over previous
#include <cuda_runtime.h>
#include <cuda_fp16.h>
#include <stdint.h>

// Problem constants
#define CB 2
#define CL 2048
#define CD 1024
#define CH 16
#define CDK 64

constexpr int  BHn        = CB * CH;               // 32
constexpr long PROJ_ELEMS = (long)CB * CL * CD;    // 4,194,304
constexpr long S_ELEMS    = (long)BHn * CL * CL;   // 134,217,728
constexpr long ZN         = (long)BHn * CL;        // 65,536
constexpr long TILE_U4    = 32768;                 // uint4 per 128x2048 fp16 E tile

// Scratch (static device globals -- no runtime allocation)
__device__ __half g_Qh[PROJ_ELEMS];                // Q proj -> normalized, fp16
__device__ __half g_Kh[PROJ_ELEMS];                // K proj -> normalized, fp16
__device__ __half g_Vh[PROJ_ELEMS];                // V projection, fp16
__device__ __half g_E[S_ELEMS];                    // exp(scores), fp16, fragment order
__device__ float  g_invZ[ZN];

// ---------------------------------------------------------------------------
// helpers
// ---------------------------------------------------------------------------
__device__ __forceinline__ void mma16h(float* d, const uint32_t* a, const uint32_t* b) {
    asm volatile(
        "mma.sync.aligned.m16n8k16.row.col.f32.f16.f16.f32 "
        "{%0,%1,%2,%3}, {%4,%5,%6,%7}, {%8,%9}, {%0,%1,%2,%3};"
        : "+f"(d[0]), "+f"(d[1]), "+f"(d[2]), "+f"(d[3])
        : "r"(a[0]), "r"(a[1]), "r"(a[2]), "r"(a[3]), "r"(b[0]), "r"(b[1]));
}

__device__ __forceinline__ uint32_t sptr(const void* p) {
    return (uint32_t)__cvta_generic_to_shared(p);
}

__device__ __forceinline__ void ldm4(uint32_t* a, uint32_t addr) {
    asm volatile("ldmatrix.sync.aligned.m8n8.x4.shared.b16 {%0,%1,%2,%3}, [%4];"
                 : "=r"(a[0]), "=r"(a[1]), "=r"(a[2]), "=r"(a[3]) : "r"(addr));
}

__device__ __forceinline__ void ldm4t(uint32_t* a, uint32_t addr) {
    asm volatile("ldmatrix.sync.aligned.m8n8.x4.trans.shared.b16 {%0,%1,%2,%3}, [%4];"
                 : "=r"(a[0]), "=r"(a[1]), "=r"(a[2]), "=r"(a[3]) : "r"(addr));
}

// ---------------------------------------------------------------------------
// fp16-MMA NT projection GEMM: C[m,n] = half( sum_k A[m,k]*B[n,k] )
// BM=64, BN=128, BK=32, 256 threads (2x4 warps), ldmatrix, fp32 accum.
// ---------------------------------------------------------------------------
__global__ __launch_bounds__(256) void proj_h_kernel(
    const float* __restrict__ A, const float* __restrict__ B,
    __half* __restrict__ C)
{
    __shared__ __half As[64][40];
    __shared__ __half Bs[128][40];

    const float* Ab = A + (long)blockIdx.y * 64 * CD;
    const float* Bb = B + (long)blockIdx.x * 128 * CD;

    const int tid  = threadIdx.x;
    const int w    = tid >> 5, lane = tid & 31;
    const int wm   = w >> 2, wn = w & 3;
    const int g    = lane >> 2, tig = lane & 3;

    float acc[2][4][4];
    #pragma unroll
    for (int i = 0; i < 2; i++)
        #pragma unroll
        for (int j = 0; j < 4; j++)
            #pragma unroll
            for (int r = 0; r < 4; r++) acc[i][j][r] = 0.f;

    float4 pa[2], pb[4];
    #pragma unroll
    for (int j = 0; j < 2; j++) {
        int s = tid + 256 * j;
        pa[j] = *(const float4*)(Ab + (long)(s >> 3) * CD + (s & 7) * 4);
    }
    #pragma unroll
    for (int j = 0; j < 4; j++) {
        int s = tid + 256 * j;
        pb[j] = *(const float4*)(Bb + (long)(s >> 3) * CD + (s & 7) * 4);
    }

    for (int k0 = 0; k0 < CD; k0 += 32) {
        #pragma unroll
        for (int j = 0; j < 2; j++) {
            int s = tid + 256 * j;
            int r = s >> 3, c = (s & 7) * 4;
            As[r][c + 0] = __float2half(pa[j].x);
            As[r][c + 1] = __float2half(pa[j].y);
            As[r][c + 2] = __float2half(pa[j].z);
            As[r][c + 3] = __float2half(pa[j].w);
        }
        #pragma unroll
        for (int j = 0; j < 4; j++) {
            int s = tid + 256 * j;
            int r = s >> 3, c = (s & 7) * 4;
            Bs[r][c + 0] = __float2half(pb[j].x);
            Bs[r][c + 1] = __float2half(pb[j].y);
            Bs[r][c + 2] = __float2half(pb[j].z);
            Bs[r][c + 3] = __float2half(pb[j].w);
        }
        __syncthreads();

        if (k0 + 32 < CD) {
            #pragma unroll
            for (int j = 0; j < 2; j++) {
                int s = tid + 256 * j;
                pa[j] = *(const float4*)(Ab + (long)(s >> 3) * CD + k0 + 32 + (s & 7) * 4);
            }
            #pragma unroll
            for (int j = 0; j < 4; j++) {
                int s = tid + 256 * j;
                pb[j] = *(const float4*)(Bb + (long)(s >> 3) * CD + k0 + 32 + (s & 7) * 4);
            }
        }

        #pragma unroll
        for (int ks = 0; ks < 2; ks++) {
            const int c0 = ks * 16;
            uint32_t af[2][4], bf[4][2];
            #pragma unroll
            for (int mt = 0; mt < 2; mt++)
                ldm4(af[mt], sptr(&As[wm * 32 + mt * 16 + (lane & 15)][c0 + (lane >> 4) * 8]));
            #pragma unroll
            for (int nh = 0; nh < 2; nh++) {
                uint32_t r4[4];
                ldm4(r4, sptr(&Bs[wn * 32 + nh * 16 + (lane & 15)][c0 + (lane >> 4) * 8]));
                bf[2 * nh][0]     = r4[0]; bf[2 * nh][1]     = r4[2];
                bf[2 * nh + 1][0] = r4[1]; bf[2 * nh + 1][1] = r4[3];
            }
            #pragma unroll
            for (int mt = 0; mt < 2; mt++)
                #pragma unroll
                for (int nt = 0; nt < 4; nt++)
                    mma16h(acc[mt][nt], af[mt], bf[nt]);
        }
        __syncthreads();
    }

    __half* Cb = C + (long)blockIdx.y * 64 * CD + (long)blockIdx.x * 128;
    #pragma unroll
    for (int mt = 0; mt < 2; mt++)
        #pragma unroll
        for (int nt = 0; nt < 4; nt++) {
            long r0  = wm * 32 + mt * 16 + g;
            int  col = wn * 32 + nt * 8 + 2 * tig;
            *(__half2*)&Cb[r0 * CD + col] =
                __floats2half2_rn(acc[mt][nt][0], acc[mt][nt][1]);
            *(__half2*)&Cb[(r0 + 8) * CD + col] =
                __floats2half2_rn(acc[mt][nt][2], acc[mt][nt][3]);
        }
}

// ---------------------------------------------------------------------------
// In-place L2 normalize of each 64-half segment; one warp per segment.
// blockIdx.y selects tensor: 0 -> Q (coef 0.125), 1 -> K (coef 1).
// ---------------------------------------------------------------------------
__global__ __launch_bounds__(256) void l2norm_h_kernel(__half* __restrict__ Q,
                                                       __half* __restrict__ K)
{
    __half* X = blockIdx.y ? K : Q;
    const float coef = blockIdx.y ? 1.0f : 0.125f;
    const int seg  = blockIdx.x * 8 + (threadIdx.x >> 5);
    const int lane = threadIdx.x & 31;
    __half2* p = (__half2*)(X + (long)seg * 64) + lane;
    float2 u = __half22float2(*p);
    float ss = u.x * u.x + u.y * u.y;
    #pragma unroll
    for (int o = 16; o; o >>= 1) ss += __shfl_xor_sync(0xffffffffu, ss, o);
    const float s = coef / fmaxf(sqrtf(ss), 1e-12f);
    *p = __floats2half2_rn(u.x * s, u.y * s);
}

// ---------------------------------------------------------------------------
// Fused flash attention (no-max softmax; scores bounded by 1/8):
// per (b,h,128-q tile): loop 64-k tiles: S=Q.K^T (fp16 MMA), E=exp(S) ->
// fragment-order fp16 gmem tile (dense uint4 stores) + register repack ->
// O += E.V (fp16 MMA), Z += rowsum(E).  Epilogue: out = O/Z; invZ stored.
// 256 threads = 8 warps, each warp owns 16 q rows.  grid (CL/128, BHn).
// ---------------------------------------------------------------------------
__global__ __launch_bounds__(256) void flash_kernel(
    const __half* __restrict__ Qh, const __half* __restrict__ Kh,
    const __half* __restrict__ Vh, __half* __restrict__ E,
    float* __restrict__ invZ, float* __restrict__ out)
{
    __shared__ __half Qs[128][72];
    __shared__ __half Ks[64][72];
    __shared__ __half Vs[64][72];

    const int z = blockIdx.y, b = z >> 4, h = z & 15;
    const int qbase = blockIdx.x * 128;
    const int tid = threadIdx.x, w = tid >> 5, lane = tid & 31;
    const int g = lane >> 2, tig = lane & 3;

    // stage Q tile, pull per-warp A fragments (held for the whole kernel)
    const __half* Qg = Qh + ((long)b * CL + qbase) * CD + h * 64;
    #pragma unroll
    for (int j = 0; j < 4; j++) {
        int f = tid + 256 * j;
        int r = f >> 3, c = (f & 7) * 8;
        *(uint4*)&Qs[r][c] = *(const uint4*)(Qg + (long)r * CD + c);
    }
    __syncthreads();
    uint32_t aq[4][4];
    #pragma unroll
    for (int kc = 0; kc < 4; kc++)
        ldm4(aq[kc], sptr(&Qs[w * 16 + (lane & 15)][kc * 16 + (lane >> 4) * 8]));

    const __half* Kg = Kh + (long)b * CL * CD + h * 64;
    const __half* Vg = Vh + (long)b * CL * CD + h * 64;

    float acc_o[8][4];
    #pragma unroll
    for (int i = 0; i < 8; i++)
        #pragma unroll
        for (int r = 0; r < 4; r++) acc_o[i][r] = 0.f;
    float zr0 = 0.f, zr1 = 0.f;

    uint4 pk[2], pv[2];
    #pragma unroll
    for (int j = 0; j < 2; j++) {
        int f = tid + 256 * j;
        int r = f >> 3, c = (f & 7) * 8;
        pk[j] = *(const uint4*)(Kg + (long)r * CD + c);
        pv[j] = *(const uint4*)(Vg + (long)r * CD + c);
    }

    // fragment-order E tile base (uint4 units)
    uint4* Etile = (uint4*)E + ((long)z * (CL / 128) + blockIdx.x) * TILE_U4;

    for (int kt = 0; kt < CL / 64; kt++) {
        #pragma unroll
        for (int j = 0; j < 2; j++) {
            int f = tid + 256 * j;
            int r = f >> 3, c = (f & 7) * 8;
            *(uint4*)&Ks[r][c] = pk[j];
            *(uint4*)&Vs[r][c] = pv[j];
        }
        __syncthreads();

        if (kt + 1 < CL / 64) {
            #pragma unroll
            for (int j = 0; j < 2; j++) {
                int f = tid + 256 * j;
                int r = f >> 3, c = (f & 7) * 8;
                long row = (long)((kt + 1) * 64 + r);
                pk[j] = *(const uint4*)(Kg + row * CD + c);
                pv[j] = *(const uint4*)(Vg + row * CD + c);
            }
        }

        // scores: S[16q x 64k] per warp
        float s[8][4];
        #pragma unroll
        for (int i = 0; i < 8; i++)
            #pragma unroll
            for (int r = 0; r < 4; r++) s[i][r] = 0.f;

        #pragma unroll
        for (int kc = 0; kc < 4; kc++) {
            #pragma unroll
            for (int p = 0; p < 4; p++) {
                uint32_t r4[4];
                ldm4(r4, sptr(&Ks[p * 16 + (lane & 15)][kc * 16 + (lane >> 4) * 8]));
                uint32_t b0[2] = {r4[0], r4[2]}, b1[2] = {r4[1], r4[3]};
                mma16h(s[2 * p],     aq[kc], b0);
                mma16h(s[2 * p + 1], aq[kc], b1);
            }
        }

        // exp + fp16 repack + row sums
        uint32_t ehlo[8], ehhi[8];
        #pragma unroll
        for (int nt = 0; nt < 8; nt++) {
            float e0 = __expf(s[nt][0]);
            float e1 = __expf(s[nt][1]);
            float e2 = __expf(s[nt][2]);
            float e3 = __expf(s[nt][3]);
            __half2 lo = __floats2half2_rn(e0, e1);
            __half2 hi = __floats2half2_rn(e2, e3);
            ehlo[nt] = *(uint32_t*)&lo;
            ehhi[nt] = *(uint32_t*)&hi;
            zr0 += e0 + e1;
            zr1 += e2 + e3;
        }

        // dense fragment-order E stores: 4 x uint4, each warp inst = 512B
        {
            uint4* p = Etile + (long)kt * 1024 + tid;
            __stcs(p,       make_uint4(ehlo[0], ehhi[0], ehlo[1], ehhi[1]));
            __stcs(p + 256, make_uint4(ehlo[2], ehhi[2], ehlo[3], ehhi[3]));
            __stcs(p + 512, make_uint4(ehlo[4], ehhi[4], ehlo[5], ehhi[5]));
            __stcs(p + 768, make_uint4(ehlo[6], ehhi[6], ehlo[7], ehhi[7]));
        }

        // PV: O += E . V  (B via ldmatrix.trans on V[k][n])
        #pragma unroll
        for (int kc = 0; kc < 4; kc++) {
            uint32_t a[4] = {ehlo[2 * kc], ehhi[2 * kc], ehlo[2 * kc + 1], ehhi[2 * kc + 1]};
            #pragma unroll
            for (int p = 0; p < 4; p++) {
                uint32_t r4[4];
                ldm4t(r4, sptr(&Vs[kc * 16 + (lane & 15)][p * 16 + (lane >> 4) * 8]));
                uint32_t b0[2] = {r4[0], r4[1]}, b1[2] = {r4[2], r4[3]};
                mma16h(acc_o[2 * p],     a, b0);
                mma16h(acc_o[2 * p + 1], a, b1);
            }
        }
        __syncthreads();
    }

    // row sums across the 4 tig lanes (fixed order), then normalize + write
    zr0 += __shfl_xor_sync(0xffffffffu, zr0, 1);
    zr0 += __shfl_xor_sync(0xffffffffu, zr0, 2);
    zr1 += __shfl_xor_sync(0xffffffffu, zr1, 1);
    zr1 += __shfl_xor_sync(0xffffffffu, zr1, 2);
    const float iz0 = 1.0f / zr0;
    const float iz1 = 1.0f / zr1;
    if (tig == 0) {
        invZ[(long)z * CL + qbase + w * 16 + g]     = iz0;
        invZ[(long)z * CL + qbase + w * 16 + g + 8] = iz1;
    }
    float* Ob = out + (long)z * CL * CDK + (long)(qbase + w * 16) * CDK;
    #pragma unroll
    for (int nt = 0; nt < 8; nt++) {
        int col = nt * 8 + 2 * tig;
        *(float2*)&Ob[(long)g * CDK + col] =
            make_float2(acc_o[nt][0] * iz0, acc_o[nt][1] * iz0);
        *(float2*)&Ob[(long)(g + 8) * CDK + col] =
            make_float2(acc_o[nt][2] * iz1, acc_o[nt][3] * iz1);
    }
}

// ---------------------------------------------------------------------------
// avg from fragment-order E:  avg[b,q,k] = (1/16) sum_h invZ[h,q]*E_h[q,k].
// Mirrors flash's exact thread->(q,k) mapping, so accumulation across heads
// happens fragment-aligned in registers.  grid (CL/128 ktgroups of 2 kt,
// CL/128 qtiles, CB); 256 threads.
// ---------------------------------------------------------------------------
__global__ __launch_bounds__(256) void avg_kernel(const __half* __restrict__ E,
                                                  const float* __restrict__ invZ,
                                                  float* __restrict__ avg)
{
    const int b   = blockIdx.z;
    const int qt  = blockIdx.y;
    const int ktg = blockIdx.x;
    const int tid = threadIdx.x, w = tid >> 5, lane = tid & 31;
    const int g = lane >> 2, tig = lane & 3;
    const int row0 = qt * 128 + w * 16 + g;

    // hoist per-head weights for this thread's two q rows
    float W0[CH], W1[CH];
    #pragma unroll
    for (int h = 0; h < CH; h++) {
        W0[h] = invZ[(long)(b * CH + h) * CL + row0]     * (1.0f / CH);
        W1[h] = invZ[(long)(b * CH + h) * CL + row0 + 8] * (1.0f / CH);
    }

    #pragma unroll
    for (int kk = 0; kk < 2; kk++) {
        const int kt = ktg * 2 + kk;
        float2 aLo[8], aHi[8];
        #pragma unroll
        for (int i = 0; i < 8; i++) {
            aLo[i] = make_float2(0.f, 0.f);
            aHi[i] = make_float2(0.f, 0.f);
        }

        #pragma unroll
        for (int h = 0; h < CH; h++) {
            const uint4* p = (const uint4*)E
                + ((long)(b * CH + h) * (CL / 128) + qt) * TILE_U4
                + (long)kt * 1024 + tid;
            const float w0 = W0[h], w1 = W1[h];
            #pragma unroll
            for (int j = 0; j < 4; j++) {
                uint4 u = __ldcs(p + j * 256);
                float2 f;
                f = __half22float2(*(__half2*)&u.x);
                aLo[2 * j].x     = fmaf(w0, f.x, aLo[2 * j].x);
                aLo[2 * j].y     = fmaf(w0, f.y, aLo[2 * j].y);
                f = __half22float2(*(__half2*)&u.y);
                aHi[2 * j].x     = fmaf(w1, f.x, aHi[2 * j].x);
                aHi[2 * j].y     = fmaf(w1, f.y, aHi[2 * j].y);
                f = __half22float2(*(__half2*)&u.z);
                aLo[2 * j + 1].x = fmaf(w0, f.x, aLo[2 * j + 1].x);
                aLo[2 * j + 1].y = fmaf(w0, f.y, aLo[2 * j + 1].y);
                f = __half22float2(*(__half2*)&u.w);
                aHi[2 * j + 1].x = fmaf(w1, f.x, aHi[2 * j + 1].x);
                aHi[2 * j + 1].y = fmaf(w1, f.y, aHi[2 * j + 1].y);
            }
        }

        float* A0 = avg + ((long)b * CL + row0) * CL;
        #pragma unroll
        for (int nt = 0; nt < 8; nt++) {
            int col = kt * 64 + nt * 8 + 2 * tig;
            *(float2*)&A0[col]          = aLo[nt];
            *(float2*)&A0[8L * CL + col] = aHi[nt];
        }
    }
}

// ---------------------------------------------------------------------------
extern "C" void kernel_launch(void* const* d_in, const int* in_sizes, int n_in,
                              void* d_out, int out_size)
{
    const float* q  = (const float*)d_in[0];
    const float* k  = (const float*)d_in[1];
    const float* v  = (const float*)d_in[2];
    const float* wq = (const float*)d_in[3];
    const float* wk = (const float*)d_in[4];
    const float* wv = (const float*)d_in[5];

    float* out = (float*)d_out;                        // [B,H,L,64]
    float* avg = out + (long)CB * CH * CL * CDK;       // [B,L,L]

    float  *iZ;
    __half *Qh, *Kh, *Vh, *Ep;
    cudaGetSymbolAddress((void**)&Qh, g_Qh);
    cudaGetSymbolAddress((void**)&Kh, g_Kh);
    cudaGetSymbolAddress((void**)&Vh, g_Vh);
    cudaGetSymbolAddress((void**)&Ep, g_E);
    cudaGetSymbolAddress((void**)&iZ, g_invZ);

    // 1) Projections (fp16 MMA, fp32 accumulate, fp16 out)
    dim3 pg(CD / 128, (CB * CL) / 64, 1);
    proj_h_kernel<<<pg, 256>>>(q, wq, Qh);
    proj_h_kernel<<<pg, 256>>>(k, wk, Kh);
    proj_h_kernel<<<pg, 256>>>(v, wv, Vh);

    // 2) In-place L2 normalize Q (fold 1/8) and K in one launch
    dim3 ng((CB * CL * CH) / 8, 2);
    l2norm_h_kernel<<<ng, 256>>>(Qh, Kh);

    // 3) Fused attention: fragment-order E + invZ + out
    dim3 fg(CL / 128, BHn);
    flash_kernel<<<fg, 256>>>(Qh, Kh, Vh, Ep, iZ, out);

    // 4) attn_avg from fragment-order E
    dim3 ag(CL / 128, CL / 128, CB);
    avg_kernel<<<ag, 256>>>(Ep, iZ, avg);
}

// round 12
// speedup vs baseline: 1.2155x; 1.0545x over previous
#include <cuda_runtime.h>
#include <cuda_fp16.h>
#include <stdint.h>

// Problem constants
#define CB 2
#define CL 2048
#define CD 1024
#define CH 16
#define CDK 64

constexpr int  BHn        = CB * CH;               // 32
constexpr long PROJ_ELEMS = (long)CB * CL * CD;    // 4,194,304
constexpr long S_ELEMS    = (long)BHn * CL * CL;   // 134,217,728
constexpr long ZN         = (long)BHn * CL;        // 65,536
constexpr long TILE_U4    = 32768;                 // uint4 per 128x2048 fp16 E tile

// Q gets 1/sqrt(64) * log2(e) folded into its normalization
#define QCOEF 0.18033688011112042f

// Scratch (static device globals -- no runtime allocation)
__device__ __half g_Qh[PROJ_ELEMS];                // normalized Q * QCOEF, fp16
__device__ __half g_Kh[PROJ_ELEMS];                // normalized K, fp16
__device__ __half g_Vh[PROJ_ELEMS];                // V projection, fp16
__device__ __half g_E[S_ELEMS];                    // exp(scores), fp16, fragment order
__device__ float  g_invZ[ZN];

// ---------------------------------------------------------------------------
// helpers
// ---------------------------------------------------------------------------
__device__ __forceinline__ void mma16h(float* d, const uint32_t* a, const uint32_t* b) {
    asm volatile(
        "mma.sync.aligned.m16n8k16.row.col.f32.f16.f16.f32 "
        "{%0,%1,%2,%3}, {%4,%5,%6,%7}, {%8,%9}, {%0,%1,%2,%3};"
        : "+f"(d[0]), "+f"(d[1]), "+f"(d[2]), "+f"(d[3])
        : "r"(a[0]), "r"(a[1]), "r"(a[2]), "r"(a[3]), "r"(b[0]), "r"(b[1]));
}

__device__ __forceinline__ uint32_t sptr(const void* p) {
    return (uint32_t)__cvta_generic_to_shared(p);
}

__device__ __forceinline__ void ldm4(uint32_t* a, uint32_t addr) {
    asm volatile("ldmatrix.sync.aligned.m8n8.x4.shared.b16 {%0,%1,%2,%3}, [%4];"
                 : "=r"(a[0]), "=r"(a[1]), "=r"(a[2]), "=r"(a[3]) : "r"(addr));
}

__device__ __forceinline__ void ldm4t(uint32_t* a, uint32_t addr) {
    asm volatile("ldmatrix.sync.aligned.m8n8.x4.trans.shared.b16 {%0,%1,%2,%3}, [%4];"
                 : "=r"(a[0]), "=r"(a[1]), "=r"(a[2]), "=r"(a[3]) : "r"(addr));
}

__device__ __forceinline__ float ex2(float x) {
    float y;
    asm("ex2.approx.f32 %0, %1;" : "=f"(y) : "f"(x));
    return y;
}

// ---------------------------------------------------------------------------
// Fused projection + (optional) per-head L2 norm, fp16 MMA.
// grid (8, 64, 3): z selects (input, weight, output, coef, donorm):
//   z=0: Q, norm with coef=QCOEF; z=1: K, norm coef=1; z=2: V, no norm.
// BM=64, BN=128, BK=32, 256 threads (2x4 warps), ldmatrix, fp32 accum.
// Norm is applied to fp32 accumulators (tile rows span complete 64-wide
// head segments; two warps share a segment -> shfl + 1KB smem exchange).
// ---------------------------------------------------------------------------
__global__ __launch_bounds__(256) void proj_norm_kernel(
    const float* __restrict__ qin, const float* __restrict__ kin,
    const float* __restrict__ vin,
    const float* __restrict__ wq, const float* __restrict__ wk,
    const float* __restrict__ wv,
    __half* __restrict__ Qo, __half* __restrict__ Ko, __half* __restrict__ Vo)
{
    __shared__ __half As[64][40];
    __shared__ __half Bs[128][40];
    __shared__ float  red[64][4];

    const int z = blockIdx.z;
    const float* A = (z == 0) ? qin : (z == 1) ? kin : vin;
    const float* B = (z == 0) ? wq  : (z == 1) ? wk  : wv;
    __half*      C = (z == 0) ? Qo  : (z == 1) ? Ko  : Vo;
    const bool  donorm = (z < 2);
    const float coef   = (z == 0) ? QCOEF : 1.0f;

    const float* Ab = A + (long)blockIdx.y * 64 * CD;
    const float* Bb = B + (long)blockIdx.x * 128 * CD;

    const int tid  = threadIdx.x;
    const int w    = tid >> 5, lane = tid & 31;
    const int wm   = w >> 2, wn = w & 3;
    const int g    = lane >> 2, tig = lane & 3;

    float acc[2][4][4];
    #pragma unroll
    for (int i = 0; i < 2; i++)
        #pragma unroll
        for (int j = 0; j < 4; j++)
            #pragma unroll
            for (int r = 0; r < 4; r++) acc[i][j][r] = 0.f;

    float4 pa[2], pb[4];
    #pragma unroll
    for (int j = 0; j < 2; j++) {
        int s = tid + 256 * j;
        pa[j] = *(const float4*)(Ab + (long)(s >> 3) * CD + (s & 7) * 4);
    }
    #pragma unroll
    for (int j = 0; j < 4; j++) {
        int s = tid + 256 * j;
        pb[j] = *(const float4*)(Bb + (long)(s >> 3) * CD + (s & 7) * 4);
    }

    for (int k0 = 0; k0 < CD; k0 += 32) {
        #pragma unroll
        for (int j = 0; j < 2; j++) {
            int s = tid + 256 * j;
            int r = s >> 3, c = (s & 7) * 4;
            As[r][c + 0] = __float2half(pa[j].x);
            As[r][c + 1] = __float2half(pa[j].y);
            As[r][c + 2] = __float2half(pa[j].z);
            As[r][c + 3] = __float2half(pa[j].w);
        }
        #pragma unroll
        for (int j = 0; j < 4; j++) {
            int s = tid + 256 * j;
            int r = s >> 3, c = (s & 7) * 4;
            Bs[r][c + 0] = __float2half(pb[j].x);
            Bs[r][c + 1] = __float2half(pb[j].y);
            Bs[r][c + 2] = __float2half(pb[j].z);
            Bs[r][c + 3] = __float2half(pb[j].w);
        }
        __syncthreads();

        if (k0 + 32 < CD) {
            #pragma unroll
            for (int j = 0; j < 2; j++) {
                int s = tid + 256 * j;
                pa[j] = *(const float4*)(Ab + (long)(s >> 3) * CD + k0 + 32 + (s & 7) * 4);
            }
            #pragma unroll
            for (int j = 0; j < 4; j++) {
                int s = tid + 256 * j;
                pb[j] = *(const float4*)(Bb + (long)(s >> 3) * CD + k0 + 32 + (s & 7) * 4);
            }
        }

        #pragma unroll
        for (int ks = 0; ks < 2; ks++) {
            const int c0 = ks * 16;
            uint32_t af[2][4], bf[4][2];
            #pragma unroll
            for (int mt = 0; mt < 2; mt++)
                ldm4(af[mt], sptr(&As[wm * 32 + mt * 16 + (lane & 15)][c0 + (lane >> 4) * 8]));
            #pragma unroll
            for (int nh = 0; nh < 2; nh++) {
                uint32_t r4[4];
                ldm4(r4, sptr(&Bs[wn * 32 + nh * 16 + (lane & 15)][c0 + (lane >> 4) * 8]));
                bf[2 * nh][0]     = r4[0]; bf[2 * nh][1]     = r4[2];
                bf[2 * nh + 1][0] = r4[1]; bf[2 * nh + 1][1] = r4[3];
            }
            #pragma unroll
            for (int mt = 0; mt < 2; mt++)
                #pragma unroll
                for (int nt = 0; nt < 4; nt++)
                    mma16h(acc[mt][nt], af[mt], bf[nt]);
        }
        __syncthreads();
    }

    float sc[2][2] = {{1.f, 1.f}, {1.f, 1.f}};   // [mt][row-half]
    if (donorm) {
        // per-row sum of squares over this warp's 32 columns
        #pragma unroll
        for (int mt = 0; mt < 2; mt++) {
            float sA = 0.f, sB = 0.f;
            #pragma unroll
            for (int nt = 0; nt < 4; nt++) {
                sA += acc[mt][nt][0] * acc[mt][nt][0] + acc[mt][nt][1] * acc[mt][nt][1];
                sB += acc[mt][nt][2] * acc[mt][nt][2] + acc[mt][nt][3] * acc[mt][nt][3];
            }
            #pragma unroll
            for (int o = 1; o <= 2; o <<= 1) {
                sA += __shfl_xor_sync(0xffffffffu, sA, o);
                sB += __shfl_xor_sync(0xffffffffu, sB, o);
            }
            if (tig == 0) {
                red[wm * 32 + mt * 16 + g][wn]     = sA;
                red[wm * 32 + mt * 16 + g + 8][wn] = sB;
            }
        }
        __syncthreads();
        const int seg2 = (wn >> 1) * 2;          // partner pair in red
        #pragma unroll
        for (int mt = 0; mt < 2; mt++) {
            int r0 = wm * 32 + mt * 16 + g;
            float n0 = red[r0][seg2]     + red[r0][seg2 + 1];
            float n1 = red[r0 + 8][seg2] + red[r0 + 8][seg2 + 1];
            sc[mt][0] = coef / fmaxf(sqrtf(n0), 1e-12f);
            sc[mt][1] = coef / fmaxf(sqrtf(n1), 1e-12f);
        }
    }

    __half* Cb = C + (long)blockIdx.y * 64 * CD + (long)blockIdx.x * 128;
    #pragma unroll
    for (int mt = 0; mt < 2; mt++)
        #pragma unroll
        for (int nt = 0; nt < 4; nt++) {
            long r0  = wm * 32 + mt * 16 + g;
            int  col = wn * 32 + nt * 8 + 2 * tig;
            *(__half2*)&Cb[r0 * CD + col] =
                __floats2half2_rn(acc[mt][nt][0] * sc[mt][0],
                                  acc[mt][nt][1] * sc[mt][0]);
            *(__half2*)&Cb[(r0 + 8) * CD + col] =
                __floats2half2_rn(acc[mt][nt][2] * sc[mt][1],
                                  acc[mt][nt][3] * sc[mt][1]);
        }
}

// ---------------------------------------------------------------------------
// Fused flash attention (no-max softmax; log2e folded into Q -> ex2):
// per (b,h,128-q tile): loop 64-k tiles: S'=Q'.K^T (fp16 MMA), E=2^S' ->
// fragment-order fp16 gmem tile (dense uint4 stores) + register repack ->
// O += E.V (fp16 MMA), Z += rowsum(E).  Epilogue: out = O/Z; invZ stored.
// 256 threads = 8 warps, each warp owns 16 q rows.  grid (CL/128, BHn).
// ---------------------------------------------------------------------------
__global__ __launch_bounds__(256) void flash_kernel(
    const __half* __restrict__ Qh, const __half* __restrict__ Kh,
    const __half* __restrict__ Vh, __half* __restrict__ E,
    float* __restrict__ invZ, float* __restrict__ out)
{
    __shared__ __half Qs[128][72];
    __shared__ __half Ks[64][72];
    __shared__ __half Vs[64][72];

    const int z = blockIdx.y, b = z >> 4, h = z & 15;
    const int qbase = blockIdx.x * 128;
    const int tid = threadIdx.x, w = tid >> 5, lane = tid & 31;
    const int g = lane >> 2, tig = lane & 3;

    // stage Q tile, pull per-warp A fragments (held for the whole kernel)
    const __half* Qg = Qh + ((long)b * CL + qbase) * CD + h * 64;
    #pragma unroll
    for (int j = 0; j < 4; j++) {
        int f = tid + 256 * j;
        int r = f >> 3, c = (f & 7) * 8;
        *(uint4*)&Qs[r][c] = *(const uint4*)(Qg + (long)r * CD + c);
    }
    __syncthreads();
    uint32_t aq[4][4];
    #pragma unroll
    for (int kc = 0; kc < 4; kc++)
        ldm4(aq[kc], sptr(&Qs[w * 16 + (lane & 15)][kc * 16 + (lane >> 4) * 8]));

    const __half* Kg = Kh + (long)b * CL * CD + h * 64;
    const __half* Vg = Vh + (long)b * CL * CD + h * 64;

    float acc_o[8][4];
    #pragma unroll
    for (int i = 0; i < 8; i++)
        #pragma unroll
        for (int r = 0; r < 4; r++) acc_o[i][r] = 0.f;
    float zr0 = 0.f, zr1 = 0.f;

    uint4 pk[2], pv[2];
    #pragma unroll
    for (int j = 0; j < 2; j++) {
        int f = tid + 256 * j;
        int r = f >> 3, c = (f & 7) * 8;
        pk[j] = *(const uint4*)(Kg + (long)r * CD + c);
        pv[j] = *(const uint4*)(Vg + (long)r * CD + c);
    }

    // fragment-order E tile base (uint4 units)
    uint4* Etile = (uint4*)E + ((long)z * (CL / 128) + blockIdx.x) * TILE_U4;

    for (int kt = 0; kt < CL / 64; kt++) {
        #pragma unroll
        for (int j = 0; j < 2; j++) {
            int f = tid + 256 * j;
            int r = f >> 3, c = (f & 7) * 8;
            *(uint4*)&Ks[r][c] = pk[j];
            *(uint4*)&Vs[r][c] = pv[j];
        }
        __syncthreads();

        if (kt + 1 < CL / 64) {
            #pragma unroll
            for (int j = 0; j < 2; j++) {
                int f = tid + 256 * j;
                int r = f >> 3, c = (f & 7) * 8;
                long row = (long)((kt + 1) * 64 + r);
                pk[j] = *(const uint4*)(Kg + row * CD + c);
                pv[j] = *(const uint4*)(Vg + row * CD + c);
            }
        }

        // scores: S[16q x 64k] per warp
        float s[8][4];
        #pragma unroll
        for (int i = 0; i < 8; i++)
            #pragma unroll
            for (int r = 0; r < 4; r++) s[i][r] = 0.f;

        #pragma unroll
        for (int kc = 0; kc < 4; kc++) {
            #pragma unroll
            for (int p = 0; p < 4; p++) {
                uint32_t r4[4];
                ldm4(r4, sptr(&Ks[p * 16 + (lane & 15)][kc * 16 + (lane >> 4) * 8]));
                uint32_t b0[2] = {r4[0], r4[2]}, b1[2] = {r4[1], r4[3]};
                mma16h(s[2 * p],     aq[kc], b0);
                mma16h(s[2 * p + 1], aq[kc], b1);
            }
        }

        // 2^s + fp16 repack + row sums
        uint32_t ehlo[8], ehhi[8];
        #pragma unroll
        for (int nt = 0; nt < 8; nt++) {
            float e0 = ex2(s[nt][0]);
            float e1 = ex2(s[nt][1]);
            float e2 = ex2(s[nt][2]);
            float e3 = ex2(s[nt][3]);
            __half2 lo = __floats2half2_rn(e0, e1);
            __half2 hi = __floats2half2_rn(e2, e3);
            ehlo[nt] = *(uint32_t*)&lo;
            ehhi[nt] = *(uint32_t*)&hi;
            zr0 += e0 + e1;
            zr1 += e2 + e3;
        }

        // dense fragment-order E stores: 4 x uint4, each warp inst = 512B
        {
            uint4* p = Etile + (long)kt * 1024 + tid;
            __stcs(p,       make_uint4(ehlo[0], ehhi[0], ehlo[1], ehhi[1]));
            __stcs(p + 256, make_uint4(ehlo[2], ehhi[2], ehlo[3], ehhi[3]));
            __stcs(p + 512, make_uint4(ehlo[4], ehhi[4], ehlo[5], ehhi[5]));
            __stcs(p + 768, make_uint4(ehlo[6], ehhi[6], ehlo[7], ehhi[7]));
        }

        // PV: O += E . V  (B via ldmatrix.trans on V[k][n])
        #pragma unroll
        for (int kc = 0; kc < 4; kc++) {
            uint32_t a[4] = {ehlo[2 * kc], ehhi[2 * kc], ehlo[2 * kc + 1], ehhi[2 * kc + 1]};
            #pragma unroll
            for (int p = 0; p < 4; p++) {
                uint32_t r4[4];
                ldm4t(r4, sptr(&Vs[kc * 16 + (lane & 15)][p * 16 + (lane >> 4) * 8]));
                uint32_t b0[2] = {r4[0], r4[1]}, b1[2] = {r4[2], r4[3]};
                mma16h(acc_o[2 * p],     a, b0);
                mma16h(acc_o[2 * p + 1], a, b1);
            }
        }
        __syncthreads();
    }

    // row sums across the 4 tig lanes (fixed order), then normalize + write
    zr0 += __shfl_xor_sync(0xffffffffu, zr0, 1);
    zr0 += __shfl_xor_sync(0xffffffffu, zr0, 2);
    zr1 += __shfl_xor_sync(0xffffffffu, zr1, 1);
    zr1 += __shfl_xor_sync(0xffffffffu, zr1, 2);
    const float iz0 = 1.0f / zr0;
    const float iz1 = 1.0f / zr1;
    if (tig == 0) {
        invZ[(long)z * CL + qbase + w * 16 + g]     = iz0;
        invZ[(long)z * CL + qbase + w * 16 + g + 8] = iz1;
    }
    float* Ob = out + (long)z * CL * CDK + (long)(qbase + w * 16) * CDK;
    #pragma unroll
    for (int nt = 0; nt < 8; nt++) {
        int col = nt * 8 + 2 * tig;
        *(float2*)&Ob[(long)g * CDK + col] =
            make_float2(acc_o[nt][0] * iz0, acc_o[nt][1] * iz0);
        *(float2*)&Ob[(long)(g + 8) * CDK + col] =
            make_float2(acc_o[nt][2] * iz1, acc_o[nt][3] * iz1);
    }
}

// ---------------------------------------------------------------------------
// avg from fragment-order E:  avg[b,q,k] = (1/16) sum_h invZ[h,q]*E_h[q,k].
// Mirrors flash's exact thread->(q,k) mapping.  grid (CL/128 ktgroups of 2,
// CL/128 qtiles, CB); 256 threads.
// ---------------------------------------------------------------------------
__global__ __launch_bounds__(256) void avg_kernel(const __half* __restrict__ E,
                                                  const float* __restrict__ invZ,
                                                  float* __restrict__ avg)
{
    const int b   = blockIdx.z;
    const int qt  = blockIdx.y;
    const int ktg = blockIdx.x;
    const int tid = threadIdx.x, w = tid >> 5, lane = tid & 31;
    const int g = lane >> 2, tig = lane & 3;
    const int row0 = qt * 128 + w * 16 + g;

    // hoist per-head weights for this thread's two q rows
    float W0[CH], W1[CH];
    #pragma unroll
    for (int h = 0; h < CH; h++) {
        W0[h] = invZ[(long)(b * CH + h) * CL + row0]     * (1.0f / CH);
        W1[h] = invZ[(long)(b * CH + h) * CL + row0 + 8] * (1.0f / CH);
    }

    #pragma unroll
    for (int kk = 0; kk < 2; kk++) {
        const int kt = ktg * 2 + kk;
        float2 aLo[8], aHi[8];
        #pragma unroll
        for (int i = 0; i < 8; i++) {
            aLo[i] = make_float2(0.f, 0.f);
            aHi[i] = make_float2(0.f, 0.f);
        }

        #pragma unroll
        for (int h = 0; h < CH; h++) {
            const uint4* p = (const uint4*)E
                + ((long)(b * CH + h) * (CL / 128) + qt) * TILE_U4
                + (long)kt * 1024 + tid;
            const float w0 = W0[h], w1 = W1[h];
            #pragma unroll
            for (int j = 0; j < 4; j++) {
                uint4 u = __ldcs(p + j * 256);
                float2 f;
                f = __half22float2(*(__half2*)&u.x);
                aLo[2 * j].x     = fmaf(w0, f.x, aLo[2 * j].x);
                aLo[2 * j].y     = fmaf(w0, f.y, aLo[2 * j].y);
                f = __half22float2(*(__half2*)&u.y);
                aHi[2 * j].x     = fmaf(w1, f.x, aHi[2 * j].x);
                aHi[2 * j].y     = fmaf(w1, f.y, aHi[2 * j].y);
                f = __half22float2(*(__half2*)&u.z);
                aLo[2 * j + 1].x = fmaf(w0, f.x, aLo[2 * j + 1].x);
                aLo[2 * j + 1].y = fmaf(w0, f.y, aLo[2 * j + 1].y);
                f = __half22float2(*(__half2*)&u.w);
                aHi[2 * j + 1].x = fmaf(w1, f.x, aHi[2 * j + 1].x);
                aHi[2 * j + 1].y = fmaf(w1, f.y, aHi[2 * j + 1].y);
            }
        }

        float* A0 = avg + ((long)b * CL + row0) * CL;
        #pragma unroll
        for (int nt = 0; nt < 8; nt++) {
            int col = kt * 64 + nt * 8 + 2 * tig;
            *(float2*)&A0[col]           = aLo[nt];
            *(float2*)&A0[8L * CL + col] = aHi[nt];
        }
    }
}

// ---------------------------------------------------------------------------
extern "C" void kernel_launch(void* const* d_in, const int* in_sizes, int n_in,
                              void* d_out, int out_size)
{
    const float* q  = (const float*)d_in[0];
    const float* k  = (const float*)d_in[1];
    const float* v  = (const float*)d_in[2];
    const float* wq = (const float*)d_in[3];
    const float* wk = (const float*)d_in[4];
    const float* wv = (const float*)d_in[5];

    float* out = (float*)d_out;                        // [B,H,L,64]
    float* avg = out + (long)CB * CH * CL * CDK;       // [B,L,L]

    float  *iZ;
    __half *Qh, *Kh, *Vh, *Ep;
    cudaGetSymbolAddress((void**)&Qh, g_Qh);
    cudaGetSymbolAddress((void**)&Kh, g_Kh);
    cudaGetSymbolAddress((void**)&Vh, g_Vh);
    cudaGetSymbolAddress((void**)&Ep, g_E);
    cudaGetSymbolAddress((void**)&iZ, g_invZ);

    // 1) Projections + fused per-head L2 norm, single launch (z = Q/K/V)
    dim3 pg(CD / 128, (CB * CL) / 64, 3);
    proj_norm_kernel<<<pg, 256>>>(q, k, v, wq, wk, wv, Qh, Kh, Vh);

    // 2) Fused attention: fragment-order E + invZ + out
    dim3 fg(CL / 128, BHn);
    flash_kernel<<<fg, 256>>>(Qh, Kh, Vh, Ep, iZ, out);

    // 3) attn_avg from fragment-order E
    dim3 ag(CL / 128, CL / 128, CB);
    avg_kernel<<<ag, 256>>>(Ep, iZ, avg);
}

// round 13
// speedup vs baseline: 1.3771x; 1.1329x over previous
#include <cuda_runtime.h>
#include <cuda_fp16.h>
#include <stdint.h>

// Problem constants
#define CB 2
#define CL 2048
#define CD 1024
#define CH 16
#define CDK 64

constexpr int  BHn        = CB * CH;               // 32
constexpr long PROJ_ELEMS = (long)CB * CL * CD;    // 4,194,304
constexpr long W_ELEMS    = (long)CD * CD;         // 1,048,576
constexpr long S_ELEMS    = (long)BHn * CL * CL;   // 134,217,728
constexpr long ZN         = (long)BHn * CL;        // 65,536
constexpr long TILE_U4    = 32768;                 // uint4 per 128x2048 fp16 E tile

// Q gets 1/sqrt(64) * log2(e) folded into its normalization
#define QCOEF 0.18033688011112042f

// Scratch (static device globals -- no runtime allocation)
__device__ __half g_Xh[3 * PROJ_ELEMS];            // q,k,v inputs, fp16
__device__ __half g_Wh[3 * W_ELEMS];               // wq,wk,wv weights, fp16
__device__ __half g_Qh[PROJ_ELEMS];                // normalized Q * QCOEF, fp16
__device__ __half g_Kh[PROJ_ELEMS];                // normalized K, fp16
__device__ __half g_Vh[PROJ_ELEMS];                // V projection, fp16
__device__ __half g_E[S_ELEMS];                    // exp(scores), fp16, fragment order
__device__ float  g_invZ[ZN];

// ---------------------------------------------------------------------------
// helpers
// ---------------------------------------------------------------------------
__device__ __forceinline__ void mma16h(float* d, const uint32_t* a, const uint32_t* b) {
    asm volatile(
        "mma.sync.aligned.m16n8k16.row.col.f32.f16.f16.f32 "
        "{%0,%1,%2,%3}, {%4,%5,%6,%7}, {%8,%9}, {%0,%1,%2,%3};"
        : "+f"(d[0]), "+f"(d[1]), "+f"(d[2]), "+f"(d[3])
        : "r"(a[0]), "r"(a[1]), "r"(a[2]), "r"(a[3]), "r"(b[0]), "r"(b[1]));
}

__device__ __forceinline__ uint32_t sptr(const void* p) {
    return (uint32_t)__cvta_generic_to_shared(p);
}

__device__ __forceinline__ void ldm4(uint32_t* a, uint32_t addr) {
    asm volatile("ldmatrix.sync.aligned.m8n8.x4.shared.b16 {%0,%1,%2,%3}, [%4];"
                 : "=r"(a[0]), "=r"(a[1]), "=r"(a[2]), "=r"(a[3]) : "r"(addr));
}

__device__ __forceinline__ void ldm4t(uint32_t* a, uint32_t addr) {
    asm volatile("ldmatrix.sync.aligned.m8n8.x4.trans.shared.b16 {%0,%1,%2,%3}, [%4];"
                 : "=r"(a[0]), "=r"(a[1]), "=r"(a[2]), "=r"(a[3]) : "r"(addr));
}

__device__ __forceinline__ float ex2(float x) {
    float y;
    asm("ex2.approx.f32 %0, %1;" : "=f"(y) : "f"(x));
    return y;
}

// ---------------------------------------------------------------------------
// fp32 -> fp16 conversion: z=0..2 inputs (4M elems), z=3..5 weights (1M).
// Each thread converts 8 floats (2x float4 -> 1x uint4).
// ---------------------------------------------------------------------------
__global__ __launch_bounds__(256) void cvt_kernel(
    const float* __restrict__ q, const float* __restrict__ k,
    const float* __restrict__ v,
    const float* __restrict__ wq, const float* __restrict__ wk,
    const float* __restrict__ wv,
    __half* __restrict__ Xh, __half* __restrict__ Wh)
{
    const int z = blockIdx.y;
    const float* src = (z == 0) ? q : (z == 1) ? k : (z == 2) ? v
                     : (z == 3) ? wq : (z == 4) ? wk : wv;
    const long n = (z < 3) ? PROJ_ELEMS : W_ELEMS;
    __half* dst = (z < 3) ? Xh + (long)z * PROJ_ELEMS
                          : Wh + (long)(z - 3) * W_ELEMS;
    const long i = ((long)blockIdx.x * 256 + threadIdx.x) * 8;
    if (i < n) {
        float4 a = *(const float4*)(src + i);
        float4 b = *(const float4*)(src + i + 4);
        __half2 h[4] = {__floats2half2_rn(a.x, a.y), __floats2half2_rn(a.z, a.w),
                        __floats2half2_rn(b.x, b.y), __floats2half2_rn(b.z, b.w)};
        *(uint4*)(dst + i) = *(uint4*)h;
    }
}

// ---------------------------------------------------------------------------
// Fused projection + (optional) per-head L2 norm, all-fp16 data path.
// grid (8, 64, 3): z = Q(norm,QCOEF) / K(norm,1) / V(no norm).
// BM=64, BN=128, BK=64, 256 threads (2x4 warps), uint4 smem staging,
// ldmatrix fragments, fp32 accum.  Norm applied to fp32 accumulators.
// ---------------------------------------------------------------------------
__global__ __launch_bounds__(256) void proj_norm_kernel(
    const __half* __restrict__ Xh, const __half* __restrict__ Wh,
    __half* __restrict__ Qo, __half* __restrict__ Ko, __half* __restrict__ Vo)
{
    __shared__ __half As[64][72];
    __shared__ __half Bs[128][72];
    __shared__ float  red[64][4];

    const int z = blockIdx.z;
    const __half* Ab = Xh + (long)z * PROJ_ELEMS + (long)blockIdx.y * 64 * CD;
    const __half* Bb = Wh + (long)z * W_ELEMS   + (long)blockIdx.x * 128 * CD;
    __half*       C  = (z == 0) ? Qo : (z == 1) ? Ko : Vo;
    const bool  donorm = (z < 2);
    const float coef   = (z == 0) ? QCOEF : 1.0f;

    const int tid  = threadIdx.x;
    const int w    = tid >> 5, lane = tid & 31;
    const int wm   = w >> 2, wn = w & 3;
    const int g    = lane >> 2, tig = lane & 3;

    float acc[2][4][4];
    #pragma unroll
    for (int i = 0; i < 2; i++)
        #pragma unroll
        for (int j = 0; j < 4; j++)
            #pragma unroll
            for (int r = 0; r < 4; r++) acc[i][j][r] = 0.f;

    uint4 pa[2], pb[4];
    #pragma unroll
    for (int j = 0; j < 2; j++) {
        int s = tid + 256 * j;                       // A: 64 rows x 8 uint4
        pa[j] = *(const uint4*)(Ab + (long)(s >> 3) * CD + (s & 7) * 8);
    }
    #pragma unroll
    for (int j = 0; j < 4; j++) {
        int s = tid + 256 * j;                       // B: 128 rows x 8 uint4
        pb[j] = *(const uint4*)(Bb + (long)(s >> 3) * CD + (s & 7) * 8);
    }

    for (int k0 = 0; k0 < CD; k0 += 64) {
        #pragma unroll
        for (int j = 0; j < 2; j++) {
            int s = tid + 256 * j;
            *(uint4*)&As[s >> 3][(s & 7) * 8] = pa[j];
        }
        #pragma unroll
        for (int j = 0; j < 4; j++) {
            int s = tid + 256 * j;
            *(uint4*)&Bs[s >> 3][(s & 7) * 8] = pb[j];
        }
        __syncthreads();

        if (k0 + 64 < CD) {
            #pragma unroll
            for (int j = 0; j < 2; j++) {
                int s = tid + 256 * j;
                pa[j] = *(const uint4*)(Ab + (long)(s >> 3) * CD + k0 + 64 + (s & 7) * 8);
            }
            #pragma unroll
            for (int j = 0; j < 4; j++) {
                int s = tid + 256 * j;
                pb[j] = *(const uint4*)(Bb + (long)(s >> 3) * CD + k0 + 64 + (s & 7) * 8);
            }
        }

        #pragma unroll
        for (int ks = 0; ks < 4; ks++) {
            const int c0 = ks * 16;
            uint32_t af[2][4], bf[4][2];
            #pragma unroll
            for (int mt = 0; mt < 2; mt++)
                ldm4(af[mt], sptr(&As[wm * 32 + mt * 16 + (lane & 15)][c0 + (lane >> 4) * 8]));
            #pragma unroll
            for (int nh = 0; nh < 2; nh++) {
                uint32_t r4[4];
                ldm4(r4, sptr(&Bs[wn * 32 + nh * 16 + (lane & 15)][c0 + (lane >> 4) * 8]));
                bf[2 * nh][0]     = r4[0]; bf[2 * nh][1]     = r4[2];
                bf[2 * nh + 1][0] = r4[1]; bf[2 * nh + 1][1] = r4[3];
            }
            #pragma unroll
            for (int mt = 0; mt < 2; mt++)
                #pragma unroll
                for (int nt = 0; nt < 4; nt++)
                    mma16h(acc[mt][nt], af[mt], bf[nt]);
        }
        __syncthreads();
    }

    float sc[2][2] = {{1.f, 1.f}, {1.f, 1.f}};   // [mt][row-half]
    if (donorm) {
        #pragma unroll
        for (int mt = 0; mt < 2; mt++) {
            float sA = 0.f, sB = 0.f;
            #pragma unroll
            for (int nt = 0; nt < 4; nt++) {
                sA += acc[mt][nt][0] * acc[mt][nt][0] + acc[mt][nt][1] * acc[mt][nt][1];
                sB += acc[mt][nt][2] * acc[mt][nt][2] + acc[mt][nt][3] * acc[mt][nt][3];
            }
            #pragma unroll
            for (int o = 1; o <= 2; o <<= 1) {
                sA += __shfl_xor_sync(0xffffffffu, sA, o);
                sB += __shfl_xor_sync(0xffffffffu, sB, o);
            }
            if (tig == 0) {
                red[wm * 32 + mt * 16 + g][wn]     = sA;
                red[wm * 32 + mt * 16 + g + 8][wn] = sB;
            }
        }
        __syncthreads();
        const int seg2 = (wn >> 1) * 2;          // partner pair in red
        #pragma unroll
        for (int mt = 0; mt < 2; mt++) {
            int r0 = wm * 32 + mt * 16 + g;
            float n0 = red[r0][seg2]     + red[r0][seg2 + 1];
            float n1 = red[r0 + 8][seg2] + red[r0 + 8][seg2 + 1];
            sc[mt][0] = coef / fmaxf(sqrtf(n0), 1e-12f);
            sc[mt][1] = coef / fmaxf(sqrtf(n1), 1e-12f);
        }
    }

    __half* Cb = C + (long)blockIdx.y * 64 * CD + (long)blockIdx.x * 128;
    #pragma unroll
    for (int mt = 0; mt < 2; mt++)
        #pragma unroll
        for (int nt = 0; nt < 4; nt++) {
            long r0  = wm * 32 + mt * 16 + g;
            int  col = wn * 32 + nt * 8 + 2 * tig;
            *(__half2*)&Cb[r0 * CD + col] =
                __floats2half2_rn(acc[mt][nt][0] * sc[mt][0],
                                  acc[mt][nt][1] * sc[mt][0]);
            *(__half2*)&Cb[(r0 + 8) * CD + col] =
                __floats2half2_rn(acc[mt][nt][2] * sc[mt][1],
                                  acc[mt][nt][3] * sc[mt][1]);
        }
}

// ---------------------------------------------------------------------------
// Fused flash attention (no-max softmax; log2e folded into Q -> ex2):
// per (b,h,128-q tile): loop 64-k tiles: S'=Q'.K^T (fp16 MMA), E=2^S' ->
// fragment-order fp16 gmem tile (dense uint4 stores) + register repack ->
// O += E.V (fp16 MMA), Z += rowsum(E).  Epilogue: out = O/Z; invZ stored.
// 256 threads = 8 warps, each warp owns 16 q rows.  grid (CL/128, BHn).
// ---------------------------------------------------------------------------
__global__ __launch_bounds__(256) void flash_kernel(
    const __half* __restrict__ Qh, const __half* __restrict__ Kh,
    const __half* __restrict__ Vh, __half* __restrict__ E,
    float* __restrict__ invZ, float* __restrict__ out)
{
    __shared__ __half Qs[128][72];
    __shared__ __half Ks[64][72];
    __shared__ __half Vs[64][72];

    const int z = blockIdx.y, b = z >> 4, h = z & 15;
    const int qbase = blockIdx.x * 128;
    const int tid = threadIdx.x, w = tid >> 5, lane = tid & 31;
    const int g = lane >> 2, tig = lane & 3;

    const __half* Qg = Qh + ((long)b * CL + qbase) * CD + h * 64;
    #pragma unroll
    for (int j = 0; j < 4; j++) {
        int f = tid + 256 * j;
        int r = f >> 3, c = (f & 7) * 8;
        *(uint4*)&Qs[r][c] = *(const uint4*)(Qg + (long)r * CD + c);
    }
    __syncthreads();
    uint32_t aq[4][4];
    #pragma unroll
    for (int kc = 0; kc < 4; kc++)
        ldm4(aq[kc], sptr(&Qs[w * 16 + (lane & 15)][kc * 16 + (lane >> 4) * 8]));

    const __half* Kg = Kh + (long)b * CL * CD + h * 64;
    const __half* Vg = Vh + (long)b * CL * CD + h * 64;

    float acc_o[8][4];
    #pragma unroll
    for (int i = 0; i < 8; i++)
        #pragma unroll
        for (int r = 0; r < 4; r++) acc_o[i][r] = 0.f;
    float zr0 = 0.f, zr1 = 0.f;

    uint4 pk[2], pv[2];
    #pragma unroll
    for (int j = 0; j < 2; j++) {
        int f = tid + 256 * j;
        int r = f >> 3, c = (f & 7) * 8;
        pk[j] = *(const uint4*)(Kg + (long)r * CD + c);
        pv[j] = *(const uint4*)(Vg + (long)r * CD + c);
    }

    uint4* Etile = (uint4*)E + ((long)z * (CL / 128) + blockIdx.x) * TILE_U4;

    for (int kt = 0; kt < CL / 64; kt++) {
        #pragma unroll
        for (int j = 0; j < 2; j++) {
            int f = tid + 256 * j;
            int r = f >> 3, c = (f & 7) * 8;
            *(uint4*)&Ks[r][c] = pk[j];
            *(uint4*)&Vs[r][c] = pv[j];
        }
        __syncthreads();

        if (kt + 1 < CL / 64) {
            #pragma unroll
            for (int j = 0; j < 2; j++) {
                int f = tid + 256 * j;
                int r = f >> 3, c = (f & 7) * 8;
                long row = (long)((kt + 1) * 64 + r);
                pk[j] = *(const uint4*)(Kg + row * CD + c);
                pv[j] = *(const uint4*)(Vg + row * CD + c);
            }
        }

        float s[8][4];
        #pragma unroll
        for (int i = 0; i < 8; i++)
            #pragma unroll
            for (int r = 0; r < 4; r++) s[i][r] = 0.f;

        #pragma unroll
        for (int kc = 0; kc < 4; kc++) {
            #pragma unroll
            for (int p = 0; p < 4; p++) {
                uint32_t r4[4];
                ldm4(r4, sptr(&Ks[p * 16 + (lane & 15)][kc * 16 + (lane >> 4) * 8]));
                uint32_t b0[2] = {r4[0], r4[2]}, b1[2] = {r4[1], r4[3]};
                mma16h(s[2 * p],     aq[kc], b0);
                mma16h(s[2 * p + 1], aq[kc], b1);
            }
        }

        uint32_t ehlo[8], ehhi[8];
        #pragma unroll
        for (int nt = 0; nt < 8; nt++) {
            float e0 = ex2(s[nt][0]);
            float e1 = ex2(s[nt][1]);
            float e2 = ex2(s[nt][2]);
            float e3 = ex2(s[nt][3]);
            __half2 lo = __floats2half2_rn(e0, e1);
            __half2 hi = __floats2half2_rn(e2, e3);
            ehlo[nt] = *(uint32_t*)&lo;
            ehhi[nt] = *(uint32_t*)&hi;
            zr0 += e0 + e1;
            zr1 += e2 + e3;
        }

        {
            uint4* p = Etile + (long)kt * 1024 + tid;
            __stcs(p,       make_uint4(ehlo[0], ehhi[0], ehlo[1], ehhi[1]));
            __stcs(p + 256, make_uint4(ehlo[2], ehhi[2], ehlo[3], ehhi[3]));
            __stcs(p + 512, make_uint4(ehlo[4], ehhi[4], ehlo[5], ehhi[5]));
            __stcs(p + 768, make_uint4(ehlo[6], ehhi[6], ehlo[7], ehhi[7]));
        }

        #pragma unroll
        for (int kc = 0; kc < 4; kc++) {
            uint32_t a[4] = {ehlo[2 * kc], ehhi[2 * kc], ehlo[2 * kc + 1], ehhi[2 * kc + 1]};
            #pragma unroll
            for (int p = 0; p < 4; p++) {
                uint32_t r4[4];
                ldm4t(r4, sptr(&Vs[kc * 16 + (lane & 15)][p * 16 + (lane >> 4) * 8]));
                uint32_t b0[2] = {r4[0], r4[1]}, b1[2] = {r4[2], r4[3]};
                mma16h(acc_o[2 * p],     a, b0);
                mma16h(acc_o[2 * p + 1], a, b1);
            }
        }
        __syncthreads();
    }

    zr0 += __shfl_xor_sync(0xffffffffu, zr0, 1);
    zr0 += __shfl_xor_sync(0xffffffffu, zr0, 2);
    zr1 += __shfl_xor_sync(0xffffffffu, zr1, 1);
    zr1 += __shfl_xor_sync(0xffffffffu, zr1, 2);
    const float iz0 = 1.0f / zr0;
    const float iz1 = 1.0f / zr1;
    if (tig == 0) {
        invZ[(long)z * CL + qbase + w * 16 + g]     = iz0;
        invZ[(long)z * CL + qbase + w * 16 + g + 8] = iz1;
    }
    float* Ob = out + (long)z * CL * CDK + (long)(qbase + w * 16) * CDK;
    #pragma unroll
    for (int nt = 0; nt < 8; nt++) {
        int col = nt * 8 + 2 * tig;
        *(float2*)&Ob[(long)g * CDK + col] =
            make_float2(acc_o[nt][0] * iz0, acc_o[nt][1] * iz0);
        *(float2*)&Ob[(long)(g + 8) * CDK + col] =
            make_float2(acc_o[nt][2] * iz1, acc_o[nt][3] * iz1);
    }
}

// ---------------------------------------------------------------------------
// avg from fragment-order E:  avg[b,q,k] = (1/16) sum_h invZ[h,q]*E_h[q,k].
// Mirrors flash's exact thread->(q,k) mapping.  grid (CL/128 ktgroups of 2,
// CL/128 qtiles, CB); 256 threads.
// ---------------------------------------------------------------------------
__global__ __launch_bounds__(256) void avg_kernel(const __half* __restrict__ E,
                                                  const float* __restrict__ invZ,
                                                  float* __restrict__ avg)
{
    const int b   = blockIdx.z;
    const int qt  = blockIdx.y;
    const int ktg = blockIdx.x;
    const int tid = threadIdx.x, w = tid >> 5, lane = tid & 31;
    const int g = lane >> 2, tig = lane & 3;
    const int row0 = qt * 128 + w * 16 + g;

    float W0[CH], W1[CH];
    #pragma unroll
    for (int h = 0; h < CH; h++) {
        W0[h] = invZ[(long)(b * CH + h) * CL + row0]     * (1.0f / CH);
        W1[h] = invZ[(long)(b * CH + h) * CL + row0 + 8] * (1.0f / CH);
    }

    #pragma unroll
    for (int kk = 0; kk < 2; kk++) {
        const int kt = ktg * 2 + kk;
        float2 aLo[8], aHi[8];
        #pragma unroll
        for (int i = 0; i < 8; i++) {
            aLo[i] = make_float2(0.f, 0.f);
            aHi[i] = make_float2(0.f, 0.f);
        }

        #pragma unroll
        for (int h = 0; h < CH; h++) {
            const uint4* p = (const uint4*)E
                + ((long)(b * CH + h) * (CL / 128) + qt) * TILE_U4
                + (long)kt * 1024 + tid;
            const float w0 = W0[h], w1 = W1[h];
            #pragma unroll
            for (int j = 0; j < 4; j++) {
                uint4 u = __ldcs(p + j * 256);
                float2 f;
                f = __half22float2(*(__half2*)&u.x);
                aLo[2 * j].x     = fmaf(w0, f.x, aLo[2 * j].x);
                aLo[2 * j].y     = fmaf(w0, f.y, aLo[2 * j].y);
                f = __half22float2(*(__half2*)&u.y);
                aHi[2 * j].x     = fmaf(w1, f.x, aHi[2 * j].x);
                aHi[2 * j].y     = fmaf(w1, f.y, aHi[2 * j].y);
                f = __half22float2(*(__half2*)&u.z);
                aLo[2 * j + 1].x = fmaf(w0, f.x, aLo[2 * j + 1].x);
                aLo[2 * j + 1].y = fmaf(w0, f.y, aLo[2 * j + 1].y);
                f = __half22float2(*(__half2*)&u.w);
                aHi[2 * j + 1].x = fmaf(w1, f.x, aHi[2 * j + 1].x);
                aHi[2 * j + 1].y = fmaf(w1, f.y, aHi[2 * j + 1].y);
            }
        }

        float* A0 = avg + ((long)b * CL + row0) * CL;
        #pragma unroll
        for (int nt = 0; nt < 8; nt++) {
            int col = kt * 64 + nt * 8 + 2 * tig;
            *(float2*)&A0[col]           = aLo[nt];
            *(float2*)&A0[8L * CL + col] = aHi[nt];
        }
    }
}

// ---------------------------------------------------------------------------
extern "C" void kernel_launch(void* const* d_in, const int* in_sizes, int n_in,
                              void* d_out, int out_size)
{
    const float* q  = (const float*)d_in[0];
    const float* k  = (const float*)d_in[1];
    const float* v  = (const float*)d_in[2];
    const float* wq = (const float*)d_in[3];
    const float* wk = (const float*)d_in[4];
    const float* wv = (const float*)d_in[5];

    float* out = (float*)d_out;                        // [B,H,L,64]
    float* avg = out + (long)CB * CH * CL * CDK;       // [B,L,L]

    float  *iZ;
    __half *Xh, *Wh, *Qh, *Kh, *Vh, *Ep;
    cudaGetSymbolAddress((void**)&Xh, g_Xh);
    cudaGetSymbolAddress((void**)&Wh, g_Wh);
    cudaGetSymbolAddress((void**)&Qh, g_Qh);
    cudaGetSymbolAddress((void**)&Kh, g_Kh);
    cudaGetSymbolAddress((void**)&Vh, g_Vh);
    cudaGetSymbolAddress((void**)&Ep, g_E);
    cudaGetSymbolAddress((void**)&iZ, g_invZ);

    // 0) fp32 -> fp16 conversion of all GEMM operands (bit-identical to the
    //    per-tile staging conversion this replaces)
    dim3 cg(PROJ_ELEMS / (256 * 8), 6);
    cvt_kernel<<<cg, 256>>>(q, k, v, wq, wk, wv, Xh, Wh);

    // 1) Projections + fused per-head L2 norm, all-fp16 data path
    dim3 pg(CD / 128, (CB * CL) / 64, 3);
    proj_norm_kernel<<<pg, 256>>>(Xh, Wh, Qh, Kh, Vh);

    // 2) Fused attention: fragment-order E + invZ + out
    dim3 fg(CL / 128, BHn);
    flash_kernel<<<fg, 256>>>(Qh, Kh, Vh, Ep, iZ, out);

    // 3) attn_avg from fragment-order E
    dim3 ag(CL / 128, CL / 128, CB);
    avg_kernel<<<ag, 256>>>(Ep, iZ, avg);
}

// round 14
// speedup vs baseline: 1.4311x; 1.0392x over previous
#include <cuda_runtime.h>
#include <cuda_fp16.h>
#include <stdint.h>

// Problem constants
#define CB 2
#define CL 2048
#define CD 1024
#define CH 16
#define CDK 64

constexpr int  BHn        = CB * CH;               // 32
constexpr long PROJ_ELEMS = (long)CB * CL * CD;    // 4,194,304
constexpr long W_ELEMS    = (long)CD * CD;         // 1,048,576
constexpr long S_ELEMS    = (long)BHn * CL * CL;   // 134,217,728
constexpr long ZN         = (long)BHn * CL;        // 65,536
constexpr long TILE_U4    = 32768;                 // uint4 per 128x2048 fp16 E tile

// Q gets 1/sqrt(64) * log2(e) folded into its normalization
#define QCOEF 0.18033688011112042f

// Scratch (static device globals -- no runtime allocation)
__device__ __half g_Xh[3 * PROJ_ELEMS];            // q,k,v inputs, fp16
__device__ __half g_Wh[3 * W_ELEMS];               // wq,wk,wv weights, fp16
__device__ __half g_Qh[PROJ_ELEMS];                // normalized Q * QCOEF, fp16
__device__ __half g_Kh[PROJ_ELEMS];                // normalized K, fp16
__device__ __half g_Vh[PROJ_ELEMS];                // V projection, fp16
__device__ __half g_E[S_ELEMS];                    // exp(scores), fp16, fragment order
__device__ float  g_invZ[ZN];

// ---------------------------------------------------------------------------
// helpers
// ---------------------------------------------------------------------------
__device__ __forceinline__ void mma16h(float* d, const uint32_t* a, const uint32_t* b) {
    asm volatile(
        "mma.sync.aligned.m16n8k16.row.col.f32.f16.f16.f32 "
        "{%0,%1,%2,%3}, {%4,%5,%6,%7}, {%8,%9}, {%0,%1,%2,%3};"
        : "+f"(d[0]), "+f"(d[1]), "+f"(d[2]), "+f"(d[3])
        : "r"(a[0]), "r"(a[1]), "r"(a[2]), "r"(a[3]), "r"(b[0]), "r"(b[1]));
}

__device__ __forceinline__ uint32_t sptr(const void* p) {
    return (uint32_t)__cvta_generic_to_shared(p);
}

__device__ __forceinline__ void ldm4(uint32_t* a, uint32_t addr) {
    asm volatile("ldmatrix.sync.aligned.m8n8.x4.shared.b16 {%0,%1,%2,%3}, [%4];"
                 : "=r"(a[0]), "=r"(a[1]), "=r"(a[2]), "=r"(a[3]) : "r"(addr));
}

__device__ __forceinline__ void ldm4t(uint32_t* a, uint32_t addr) {
    asm volatile("ldmatrix.sync.aligned.m8n8.x4.trans.shared.b16 {%0,%1,%2,%3}, [%4];"
                 : "=r"(a[0]), "=r"(a[1]), "=r"(a[2]), "=r"(a[3]) : "r"(addr));
}

__device__ __forceinline__ float ex2(float x) {
    float y;
    asm("ex2.approx.f32 %0, %1;" : "=f"(y) : "f"(x));
    return y;
}

// ---------------------------------------------------------------------------
// fp32 -> fp16 conversion: z=0..2 inputs (4M elems), z=3..5 weights (1M).
// ---------------------------------------------------------------------------
__global__ __launch_bounds__(256) void cvt_kernel(
    const float* __restrict__ q, const float* __restrict__ k,
    const float* __restrict__ v,
    const float* __restrict__ wq, const float* __restrict__ wk,
    const float* __restrict__ wv,
    __half* __restrict__ Xh, __half* __restrict__ Wh)
{
    const int z = blockIdx.y;
    const float* src = (z == 0) ? q : (z == 1) ? k : (z == 2) ? v
                     : (z == 3) ? wq : (z == 4) ? wk : wv;
    const long n = (z < 3) ? PROJ_ELEMS : W_ELEMS;
    __half* dst = (z < 3) ? Xh + (long)z * PROJ_ELEMS
                          : Wh + (long)(z - 3) * W_ELEMS;
    const long i = ((long)blockIdx.x * 256 + threadIdx.x) * 8;
    if (i < n) {
        float4 a = *(const float4*)(src + i);
        float4 b = *(const float4*)(src + i + 4);
        __half2 h[4] = {__floats2half2_rn(a.x, a.y), __floats2half2_rn(a.z, a.w),
                        __floats2half2_rn(b.x, b.y), __floats2half2_rn(b.z, b.w)};
        *(uint4*)(dst + i) = *(uint4*)h;
    }
}

// ---------------------------------------------------------------------------
// Fused projection + per-head L2 norm, all-fp16 data path.
// grid (8, 32, 3): z = Q(norm,QCOEF) / K(norm,1) / V(no norm).
// BM=128, BN=128, BK=64, 256 threads as 4x2 warps (warp = 32 rows x 64 cols).
// Each warp's 64 columns span exactly one head segment -> per-row L2 norm is
// fully in-warp (tig shfl only), applied to fp32 accumulators.
// ---------------------------------------------------------------------------
__global__ __launch_bounds__(256) void proj_norm_kernel(
    const __half* __restrict__ Xh, const __half* __restrict__ Wh,
    __half* __restrict__ Qo, __half* __restrict__ Ko, __half* __restrict__ Vo)
{
    __shared__ __half As[128][72];
    __shared__ __half Bs[128][72];

    const int z = blockIdx.z;
    const __half* Ab = Xh + (long)z * PROJ_ELEMS + (long)blockIdx.y * 128 * CD;
    const __half* Bb = Wh + (long)z * W_ELEMS   + (long)blockIdx.x * 128 * CD;
    __half*       C  = (z == 0) ? Qo : (z == 1) ? Ko : Vo;
    const bool  donorm = (z < 2);
    const float coef   = (z == 0) ? QCOEF : 1.0f;

    const int tid  = threadIdx.x;
    const int w    = tid >> 5, lane = tid & 31;
    const int wm   = w >> 1, wn = w & 1;         // 4x2 warp grid
    const int g    = lane >> 2, tig = lane & 3;

    float acc[2][8][4];
    #pragma unroll
    for (int i = 0; i < 2; i++)
        #pragma unroll
        for (int j = 0; j < 8; j++)
            #pragma unroll
            for (int r = 0; r < 4; r++) acc[i][j][r] = 0.f;

    uint4 pa[4], pb[4];
    #pragma unroll
    for (int j = 0; j < 4; j++) {
        int s = tid + 256 * j;                   // 128 rows x 8 uint4
        pa[j] = *(const uint4*)(Ab + (long)(s >> 3) * CD + (s & 7) * 8);
        pb[j] = *(const uint4*)(Bb + (long)(s >> 3) * CD + (s & 7) * 8);
    }

    for (int k0 = 0; k0 < CD; k0 += 64) {
        #pragma unroll
        for (int j = 0; j < 4; j++) {
            int s = tid + 256 * j;
            *(uint4*)&As[s >> 3][(s & 7) * 8] = pa[j];
            *(uint4*)&Bs[s >> 3][(s & 7) * 8] = pb[j];
        }
        __syncthreads();

        if (k0 + 64 < CD) {
            #pragma unroll
            for (int j = 0; j < 4; j++) {
                int s = tid + 256 * j;
                pa[j] = *(const uint4*)(Ab + (long)(s >> 3) * CD + k0 + 64 + (s & 7) * 8);
                pb[j] = *(const uint4*)(Bb + (long)(s >> 3) * CD + k0 + 64 + (s & 7) * 8);
            }
        }

        #pragma unroll
        for (int ks = 0; ks < 4; ks++) {
            const int c0 = ks * 16;
            uint32_t af[2][4], bf[8][2];
            #pragma unroll
            for (int mt = 0; mt < 2; mt++)
                ldm4(af[mt], sptr(&As[wm * 32 + mt * 16 + (lane & 15)][c0 + (lane >> 4) * 8]));
            #pragma unroll
            for (int nh = 0; nh < 4; nh++) {
                uint32_t r4[4];
                ldm4(r4, sptr(&Bs[wn * 64 + nh * 16 + (lane & 15)][c0 + (lane >> 4) * 8]));
                bf[2 * nh][0]     = r4[0]; bf[2 * nh][1]     = r4[2];
                bf[2 * nh + 1][0] = r4[1]; bf[2 * nh + 1][1] = r4[3];
            }
            #pragma unroll
            for (int mt = 0; mt < 2; mt++)
                #pragma unroll
                for (int nt = 0; nt < 8; nt++)
                    mma16h(acc[mt][nt], af[mt], bf[nt]);
        }
        __syncthreads();
    }

    float sc[2][2] = {{1.f, 1.f}, {1.f, 1.f}};   // [mt][row-half]
    if (donorm) {
        #pragma unroll
        for (int mt = 0; mt < 2; mt++) {
            float sA = 0.f, sB = 0.f;
            #pragma unroll
            for (int nt = 0; nt < 8; nt++) {
                sA += acc[mt][nt][0] * acc[mt][nt][0] + acc[mt][nt][1] * acc[mt][nt][1];
                sB += acc[mt][nt][2] * acc[mt][nt][2] + acc[mt][nt][3] * acc[mt][nt][3];
            }
            #pragma unroll
            for (int o = 1; o <= 2; o <<= 1) {
                sA += __shfl_xor_sync(0xffffffffu, sA, o);
                sB += __shfl_xor_sync(0xffffffffu, sB, o);
            }
            sc[mt][0] = coef / fmaxf(sqrtf(sA), 1e-12f);
            sc[mt][1] = coef / fmaxf(sqrtf(sB), 1e-12f);
        }
    }

    __half* Cb = C + (long)blockIdx.y * 128 * CD + (long)blockIdx.x * 128;
    #pragma unroll
    for (int mt = 0; mt < 2; mt++)
        #pragma unroll
        for (int nt = 0; nt < 8; nt++) {
            long r0  = wm * 32 + mt * 16 + g;
            int  col = wn * 64 + nt * 8 + 2 * tig;
            *(__half2*)&Cb[r0 * CD + col] =
                __floats2half2_rn(acc[mt][nt][0] * sc[mt][0],
                                  acc[mt][nt][1] * sc[mt][0]);
            *(__half2*)&Cb[(r0 + 8) * CD + col] =
                __floats2half2_rn(acc[mt][nt][2] * sc[mt][1],
                                  acc[mt][nt][3] * sc[mt][1]);
        }
}

// ---------------------------------------------------------------------------
// Fused flash attention (no-max softmax; log2e folded into Q -> ex2):
// per (b,h,128-q tile): loop 64-k tiles: S'=Q'.K^T (fp16 MMA), E=2^S' ->
// fragment-order fp16 gmem tile (dense uint4 stores) + register repack ->
// O += E.V (fp16 MMA), Z += rowsum(E).  Epilogue: out = O/Z; invZ stored.
// 256 threads = 8 warps, each warp owns 16 q rows.  grid (CL/128, BHn).
// ---------------------------------------------------------------------------
__global__ __launch_bounds__(256) void flash_kernel(
    const __half* __restrict__ Qh, const __half* __restrict__ Kh,
    const __half* __restrict__ Vh, __half* __restrict__ E,
    float* __restrict__ invZ, float* __restrict__ out)
{
    __shared__ __half Qs[128][72];
    __shared__ __half Ks[64][72];
    __shared__ __half Vs[64][72];

    const int z = blockIdx.y, b = z >> 4, h = z & 15;
    const int qbase = blockIdx.x * 128;
    const int tid = threadIdx.x, w = tid >> 5, lane = tid & 31;
    const int g = lane >> 2, tig = lane & 3;

    const __half* Qg = Qh + ((long)b * CL + qbase) * CD + h * 64;
    #pragma unroll
    for (int j = 0; j < 4; j++) {
        int f = tid + 256 * j;
        int r = f >> 3, c = (f & 7) * 8;
        *(uint4*)&Qs[r][c] = *(const uint4*)(Qg + (long)r * CD + c);
    }
    __syncthreads();
    uint32_t aq[4][4];
    #pragma unroll
    for (int kc = 0; kc < 4; kc++)
        ldm4(aq[kc], sptr(&Qs[w * 16 + (lane & 15)][kc * 16 + (lane >> 4) * 8]));

    const __half* Kg = Kh + (long)b * CL * CD + h * 64;
    const __half* Vg = Vh + (long)b * CL * CD + h * 64;

    float acc_o[8][4];
    #pragma unroll
    for (int i = 0; i < 8; i++)
        #pragma unroll
        for (int r = 0; r < 4; r++) acc_o[i][r] = 0.f;
    float zr0 = 0.f, zr1 = 0.f;

    uint4 pk[2], pv[2];
    #pragma unroll
    for (int j = 0; j < 2; j++) {
        int f = tid + 256 * j;
        int r = f >> 3, c = (f & 7) * 8;
        pk[j] = *(const uint4*)(Kg + (long)r * CD + c);
        pv[j] = *(const uint4*)(Vg + (long)r * CD + c);
    }

    uint4* Etile = (uint4*)E + ((long)z * (CL / 128) + blockIdx.x) * TILE_U4;

    for (int kt = 0; kt < CL / 64; kt++) {
        #pragma unroll
        for (int j = 0; j < 2; j++) {
            int f = tid + 256 * j;
            int r = f >> 3, c = (f & 7) * 8;
            *(uint4*)&Ks[r][c] = pk[j];
            *(uint4*)&Vs[r][c] = pv[j];
        }
        __syncthreads();

        if (kt + 1 < CL / 64) {
            #pragma unroll
            for (int j = 0; j < 2; j++) {
                int f = tid + 256 * j;
                int r = f >> 3, c = (f & 7) * 8;
                long row = (long)((kt + 1) * 64 + r);
                pk[j] = *(const uint4*)(Kg + row * CD + c);
                pv[j] = *(const uint4*)(Vg + row * CD + c);
            }
        }

        float s[8][4];
        #pragma unroll
        for (int i = 0; i < 8; i++)
            #pragma unroll
            for (int r = 0; r < 4; r++) s[i][r] = 0.f;

        #pragma unroll
        for (int kc = 0; kc < 4; kc++) {
            #pragma unroll
            for (int p = 0; p < 4; p++) {
                uint32_t r4[4];
                ldm4(r4, sptr(&Ks[p * 16 + (lane & 15)][kc * 16 + (lane >> 4) * 8]));
                uint32_t b0[2] = {r4[0], r4[2]}, b1[2] = {r4[1], r4[3]};
                mma16h(s[2 * p],     aq[kc], b0);
                mma16h(s[2 * p + 1], aq[kc], b1);
            }
        }

        uint32_t ehlo[8], ehhi[8];
        #pragma unroll
        for (int nt = 0; nt < 8; nt++) {
            float e0 = ex2(s[nt][0]);
            float e1 = ex2(s[nt][1]);
            float e2 = ex2(s[nt][2]);
            float e3 = ex2(s[nt][3]);
            __half2 lo = __floats2half2_rn(e0, e1);
            __half2 hi = __floats2half2_rn(e2, e3);
            ehlo[nt] = *(uint32_t*)&lo;
            ehhi[nt] = *(uint32_t*)&hi;
            zr0 += e0 + e1;
            zr1 += e2 + e3;
        }

        {
            uint4* p = Etile + (long)kt * 1024 + tid;
            __stcs(p,       make_uint4(ehlo[0], ehhi[0], ehlo[1], ehhi[1]));
            __stcs(p + 256, make_uint4(ehlo[2], ehhi[2], ehlo[3], ehhi[3]));
            __stcs(p + 512, make_uint4(ehlo[4], ehhi[4], ehlo[5], ehhi[5]));
            __stcs(p + 768, make_uint4(ehlo[6], ehhi[6], ehlo[7], ehhi[7]));
        }

        #pragma unroll
        for (int kc = 0; kc < 4; kc++) {
            uint32_t a[4] = {ehlo[2 * kc], ehhi[2 * kc], ehlo[2 * kc + 1], ehhi[2 * kc + 1]};
            #pragma unroll
            for (int p = 0; p < 4; p++) {
                uint32_t r4[4];
                ldm4t(r4, sptr(&Vs[kc * 16 + (lane & 15)][p * 16 + (lane >> 4) * 8]));
                uint32_t b0[2] = {r4[0], r4[1]}, b1[2] = {r4[2], r4[3]};
                mma16h(acc_o[2 * p],     a, b0);
                mma16h(acc_o[2 * p + 1], a, b1);
            }
        }
        __syncthreads();
    }

    zr0 += __shfl_xor_sync(0xffffffffu, zr0, 1);
    zr0 += __shfl_xor_sync(0xffffffffu, zr0, 2);
    zr1 += __shfl_xor_sync(0xffffffffu, zr1, 1);
    zr1 += __shfl_xor_sync(0xffffffffu, zr1, 2);
    const float iz0 = 1.0f / zr0;
    const float iz1 = 1.0f / zr1;
    if (tig == 0) {
        invZ[(long)z * CL + qbase + w * 16 + g]     = iz0;
        invZ[(long)z * CL + qbase + w * 16 + g + 8] = iz1;
    }
    float* Ob = out + (long)z * CL * CDK + (long)(qbase + w * 16) * CDK;
    #pragma unroll
    for (int nt = 0; nt < 8; nt++) {
        int col = nt * 8 + 2 * tig;
        *(float2*)&Ob[(long)g * CDK + col] =
            make_float2(acc_o[nt][0] * iz0, acc_o[nt][1] * iz0);
        *(float2*)&Ob[(long)(g + 8) * CDK + col] =
            make_float2(acc_o[nt][2] * iz1, acc_o[nt][3] * iz1);
    }
}

// ---------------------------------------------------------------------------
// avg from fragment-order E:  avg[b,q,k] = (1/16) sum_h invZ[h,q]*E_h[q,k].
// Mirrors flash's exact thread->(q,k) mapping.  grid (CL/128 ktgroups of 2,
// CL/128 qtiles, CB); 256 threads.
// ---------------------------------------------------------------------------
__global__ __launch_bounds__(256) void avg_kernel(const __half* __restrict__ E,
                                                  const float* __restrict__ invZ,
                                                  float* __restrict__ avg)
{
    const int b   = blockIdx.z;
    const int qt  = blockIdx.y;
    const int ktg = blockIdx.x;
    const int tid = threadIdx.x, w = tid >> 5, lane = tid & 31;
    const int g = lane >> 2, tig = lane & 3;
    const int row0 = qt * 128 + w * 16 + g;

    float W0[CH], W1[CH];
    #pragma unroll
    for (int h = 0; h < CH; h++) {
        W0[h] = invZ[(long)(b * CH + h) * CL + row0]     * (1.0f / CH);
        W1[h] = invZ[(long)(b * CH + h) * CL + row0 + 8] * (1.0f / CH);
    }

    #pragma unroll
    for (int kk = 0; kk < 2; kk++) {
        const int kt = ktg * 2 + kk;
        float2 aLo[8], aHi[8];
        #pragma unroll
        for (int i = 0; i < 8; i++) {
            aLo[i] = make_float2(0.f, 0.f);
            aHi[i] = make_float2(0.f, 0.f);
        }

        #pragma unroll
        for (int h = 0; h < CH; h++) {
            const uint4* p = (const uint4*)E
                + ((long)(b * CH + h) * (CL / 128) + qt) * TILE_U4
                + (long)kt * 1024 + tid;
            const float w0 = W0[h], w1 = W1[h];
            #pragma unroll
            for (int j = 0; j < 4; j++) {
                uint4 u = __ldcs(p + j * 256);
                float2 f;
                f = __half22float2(*(__half2*)&u.x);
                aLo[2 * j].x     = fmaf(w0, f.x, aLo[2 * j].x);
                aLo[2 * j].y     = fmaf(w0, f.y, aLo[2 * j].y);
                f = __half22float2(*(__half2*)&u.y);
                aHi[2 * j].x     = fmaf(w1, f.x, aHi[2 * j].x);
                aHi[2 * j].y     = fmaf(w1, f.y, aHi[2 * j].y);
                f = __half22float2(*(__half2*)&u.z);
                aLo[2 * j + 1].x = fmaf(w0, f.x, aLo[2 * j + 1].x);
                aLo[2 * j + 1].y = fmaf(w0, f.y, aLo[2 * j + 1].y);
                f = __half22float2(*(__half2*)&u.w);
                aHi[2 * j + 1].x = fmaf(w1, f.x, aHi[2 * j + 1].x);
                aHi[2 * j + 1].y = fmaf(w1, f.y, aHi[2 * j + 1].y);
            }
        }

        float* A0 = avg + ((long)b * CL + row0) * CL;
        #pragma unroll
        for (int nt = 0; nt < 8; nt++) {
            int col = kt * 64 + nt * 8 + 2 * tig;
            *(float2*)&A0[col]           = aLo[nt];
            *(float2*)&A0[8L * CL + col] = aHi[nt];
        }
    }
}

// ---------------------------------------------------------------------------
extern "C" void kernel_launch(void* const* d_in, const int* in_sizes, int n_in,
                              void* d_out, int out_size)
{
    const float* q  = (const float*)d_in[0];
    const float* k  = (const float*)d_in[1];
    const float* v  = (const float*)d_in[2];
    const float* wq = (const float*)d_in[3];
    const float* wk = (const float*)d_in[4];
    const float* wv = (const float*)d_in[5];

    float* out = (float*)d_out;                        // [B,H,L,64]
    float* avg = out + (long)CB * CH * CL * CDK;       // [B,L,L]

    float  *iZ;
    __half *Xh, *Wh, *Qh, *Kh, *Vh, *Ep;
    cudaGetSymbolAddress((void**)&Xh, g_Xh);
    cudaGetSymbolAddress((void**)&Wh, g_Wh);
    cudaGetSymbolAddress((void**)&Qh, g_Qh);
    cudaGetSymbolAddress((void**)&Kh, g_Kh);
    cudaGetSymbolAddress((void**)&Vh, g_Vh);
    cudaGetSymbolAddress((void**)&Ep, g_E);
    cudaGetSymbolAddress((void**)&iZ, g_invZ);

    // 0) fp32 -> fp16 conversion of all GEMM operands
    dim3 cg(PROJ_ELEMS / (256 * 8), 6);
    cvt_kernel<<<cg, 256>>>(q, k, v, wq, wk, wv, Xh, Wh);

    // 1) Projections + fused per-head L2 norm (BM=128, BN=128, BK=64)
    dim3 pg(CD / 128, (CB * CL) / 128, 3);
    proj_norm_kernel<<<pg, 256>>>(Xh, Wh, Qh, Kh, Vh);

    // 2) Fused attention: fragment-order E + invZ + out
    dim3 fg(CL / 128, BHn);
    flash_kernel<<<fg, 256>>>(Qh, Kh, Vh, Ep, iZ, out);

    // 3) attn_avg from fragment-order E
    dim3 ag(CL / 128, CL / 128, CB);
    avg_kernel<<<ag, 256>>>(Ep, iZ, avg);
}

// round 15
// speedup vs baseline: 1.4638x; 1.0229x over previous
#include <cuda_runtime.h>
#include <cuda_fp16.h>
#include <stdint.h>

// Problem constants
#define CB 2
#define CL 2048
#define CD 1024
#define CH 16
#define CDK 64

constexpr int  BHn        = CB * CH;               // 32
constexpr long PROJ_ELEMS = (long)CB * CL * CD;    // 4,194,304
constexpr long W_ELEMS    = (long)CD * CD;         // 1,048,576
constexpr long S_ELEMS    = (long)BHn * CL * CL;   // 134,217,728
constexpr long ZN         = (long)BHn * CL;        // 65,536
constexpr long TILE_U4    = 16384;                 // uint4 per 128x2048 uint8 E tile

// Q gets 1/sqrt(64) * log2(e) folded into its normalization
#define QCOEF 0.18033688011112042f

// uint8 E encoding: e = 2^s', s' in +-0.1803 -> e in [0.8824, 1.1335]
#define ELO    0.87f
#define EINV   910.7142857f        // 255 / 0.28
#define ESTEP  0.001098039216f     // 0.28 / 255
#define EMAGIC 8388608.0f          // 2^23

// Scratch (static device globals -- no runtime allocation)
__device__ __half  g_Xh[3 * PROJ_ELEMS];           // q,k,v inputs, fp16
__device__ __half  g_Wh[3 * W_ELEMS];              // wq,wk,wv weights, fp16
__device__ __half  g_Qh[PROJ_ELEMS];               // normalized Q * QCOEF, fp16
__device__ __half  g_Kh[PROJ_ELEMS];               // normalized K, fp16
__device__ __half  g_Vh[PROJ_ELEMS];               // V projection, fp16
__device__ uint8_t g_E8[S_ELEMS];                  // exp(scores), uint8, fragment order
__device__ float   g_invZ[ZN];

// ---------------------------------------------------------------------------
// helpers
// ---------------------------------------------------------------------------
__device__ __forceinline__ void mma16h(float* d, const uint32_t* a, const uint32_t* b) {
    asm volatile(
        "mma.sync.aligned.m16n8k16.row.col.f32.f16.f16.f32 "
        "{%0,%1,%2,%3}, {%4,%5,%6,%7}, {%8,%9}, {%0,%1,%2,%3};"
        : "+f"(d[0]), "+f"(d[1]), "+f"(d[2]), "+f"(d[3])
        : "r"(a[0]), "r"(a[1]), "r"(a[2]), "r"(a[3]), "r"(b[0]), "r"(b[1]));
}

__device__ __forceinline__ uint32_t sptr(const void* p) {
    return (uint32_t)__cvta_generic_to_shared(p);
}

__device__ __forceinline__ void ldm4(uint32_t* a, uint32_t addr) {
    asm volatile("ldmatrix.sync.aligned.m8n8.x4.shared.b16 {%0,%1,%2,%3}, [%4];"
                 : "=r"(a[0]), "=r"(a[1]), "=r"(a[2]), "=r"(a[3]) : "r"(addr));
}

__device__ __forceinline__ void ldm4t(uint32_t* a, uint32_t addr) {
    asm volatile("ldmatrix.sync.aligned.m8n8.x4.trans.shared.b16 {%0,%1,%2,%3}, [%4];"
                 : "=r"(a[0]), "=r"(a[1]), "=r"(a[2]), "=r"(a[3]) : "r"(addr));
}

__device__ __forceinline__ float ex2(float x) {
    float y;
    asm("ex2.approx.f32 %0, %1;" : "=f"(y) : "f"(x));
    return y;
}

// encode one exp value to the uint8 affine code (float bits; low byte valid)
__device__ __forceinline__ uint32_t e_enc(float e) {
    return __float_as_uint(fmaf(e - ELO, EINV, EMAGIC));
}

// ---------------------------------------------------------------------------
// fp32 -> fp16 conversion: z=0..2 inputs (4M elems), z=3..5 weights (1M).
// ---------------------------------------------------------------------------
__global__ __launch_bounds__(256) void cvt_kernel(
    const float* __restrict__ q, const float* __restrict__ k,
    const float* __restrict__ v,
    const float* __restrict__ wq, const float* __restrict__ wk,
    const float* __restrict__ wv,
    __half* __restrict__ Xh, __half* __restrict__ Wh)
{
    const int z = blockIdx.y;
    const float* src = (z == 0) ? q : (z == 1) ? k : (z == 2) ? v
                     : (z == 3) ? wq : (z == 4) ? wk : wv;
    const long n = (z < 3) ? PROJ_ELEMS : W_ELEMS;
    __half* dst = (z < 3) ? Xh + (long)z * PROJ_ELEMS
                          : Wh + (long)(z - 3) * W_ELEMS;
    const long i = ((long)blockIdx.x * 256 + threadIdx.x) * 8;
    if (i < n) {
        float4 a = *(const float4*)(src + i);
        float4 b = *(const float4*)(src + i + 4);
        __half2 h[4] = {__floats2half2_rn(a.x, a.y), __floats2half2_rn(a.z, a.w),
                        __floats2half2_rn(b.x, b.y), __floats2half2_rn(b.z, b.w)};
        *(uint4*)(dst + i) = *(uint4*)h;
    }
}

// ---------------------------------------------------------------------------
// Fused projection + per-head L2 norm, all-fp16 data path.
// BM=128, BN=128, BK=64, 256 threads as 4x2 warps.  (validated round 14)
// ---------------------------------------------------------------------------
__global__ __launch_bounds__(256) void proj_norm_kernel(
    const __half* __restrict__ Xh, const __half* __restrict__ Wh,
    __half* __restrict__ Qo, __half* __restrict__ Ko, __half* __restrict__ Vo)
{
    __shared__ __half As[128][72];
    __shared__ __half Bs[128][72];

    const int z = blockIdx.z;
    const __half* Ab = Xh + (long)z * PROJ_ELEMS + (long)blockIdx.y * 128 * CD;
    const __half* Bb = Wh + (long)z * W_ELEMS   + (long)blockIdx.x * 128 * CD;
    __half*       C  = (z == 0) ? Qo : (z == 1) ? Ko : Vo;
    const bool  donorm = (z < 2);
    const float coef   = (z == 0) ? QCOEF : 1.0f;

    const int tid  = threadIdx.x;
    const int w    = tid >> 5, lane = tid & 31;
    const int wm   = w >> 1, wn = w & 1;
    const int g    = lane >> 2, tig = lane & 3;

    float acc[2][8][4];
    #pragma unroll
    for (int i = 0; i < 2; i++)
        #pragma unroll
        for (int j = 0; j < 8; j++)
            #pragma unroll
            for (int r = 0; r < 4; r++) acc[i][j][r] = 0.f;

    uint4 pa[4], pb[4];
    #pragma unroll
    for (int j = 0; j < 4; j++) {
        int s = tid + 256 * j;
        pa[j] = *(const uint4*)(Ab + (long)(s >> 3) * CD + (s & 7) * 8);
        pb[j] = *(const uint4*)(Bb + (long)(s >> 3) * CD + (s & 7) * 8);
    }

    for (int k0 = 0; k0 < CD; k0 += 64) {
        #pragma unroll
        for (int j = 0; j < 4; j++) {
            int s = tid + 256 * j;
            *(uint4*)&As[s >> 3][(s & 7) * 8] = pa[j];
            *(uint4*)&Bs[s >> 3][(s & 7) * 8] = pb[j];
        }
        __syncthreads();

        if (k0 + 64 < CD) {
            #pragma unroll
            for (int j = 0; j < 4; j++) {
                int s = tid + 256 * j;
                pa[j] = *(const uint4*)(Ab + (long)(s >> 3) * CD + k0 + 64 + (s & 7) * 8);
                pb[j] = *(const uint4*)(Bb + (long)(s >> 3) * CD + k0 + 64 + (s & 7) * 8);
            }
        }

        #pragma unroll
        for (int ks = 0; ks < 4; ks++) {
            const int c0 = ks * 16;
            uint32_t af[2][4], bf[8][2];
            #pragma unroll
            for (int mt = 0; mt < 2; mt++)
                ldm4(af[mt], sptr(&As[wm * 32 + mt * 16 + (lane & 15)][c0 + (lane >> 4) * 8]));
            #pragma unroll
            for (int nh = 0; nh < 4; nh++) {
                uint32_t r4[4];
                ldm4(r4, sptr(&Bs[wn * 64 + nh * 16 + (lane & 15)][c0 + (lane >> 4) * 8]));
                bf[2 * nh][0]     = r4[0]; bf[2 * nh][1]     = r4[2];
                bf[2 * nh + 1][0] = r4[1]; bf[2 * nh + 1][1] = r4[3];
            }
            #pragma unroll
            for (int mt = 0; mt < 2; mt++)
                #pragma unroll
                for (int nt = 0; nt < 8; nt++)
                    mma16h(acc[mt][nt], af[mt], bf[nt]);
        }
        __syncthreads();
    }

    float sc[2][2] = {{1.f, 1.f}, {1.f, 1.f}};
    if (donorm) {
        #pragma unroll
        for (int mt = 0; mt < 2; mt++) {
            float sA = 0.f, sB = 0.f;
            #pragma unroll
            for (int nt = 0; nt < 8; nt++) {
                sA += acc[mt][nt][0] * acc[mt][nt][0] + acc[mt][nt][1] * acc[mt][nt][1];
                sB += acc[mt][nt][2] * acc[mt][nt][2] + acc[mt][nt][3] * acc[mt][nt][3];
            }
            #pragma unroll
            for (int o = 1; o <= 2; o <<= 1) {
                sA += __shfl_xor_sync(0xffffffffu, sA, o);
                sB += __shfl_xor_sync(0xffffffffu, sB, o);
            }
            sc[mt][0] = coef / fmaxf(sqrtf(sA), 1e-12f);
            sc[mt][1] = coef / fmaxf(sqrtf(sB), 1e-12f);
        }
    }

    __half* Cb = C + (long)blockIdx.y * 128 * CD + (long)blockIdx.x * 128;
    #pragma unroll
    for (int mt = 0; mt < 2; mt++)
        #pragma unroll
        for (int nt = 0; nt < 8; nt++) {
            long r0  = wm * 32 + mt * 16 + g;
            int  col = wn * 64 + nt * 8 + 2 * tig;
            *(__half2*)&Cb[r0 * CD + col] =
                __floats2half2_rn(acc[mt][nt][0] * sc[mt][0],
                                  acc[mt][nt][1] * sc[mt][0]);
            *(__half2*)&Cb[(r0 + 8) * CD + col] =
                __floats2half2_rn(acc[mt][nt][2] * sc[mt][1],
                                  acc[mt][nt][3] * sc[mt][1]);
        }
}

// ---------------------------------------------------------------------------
// Fused flash attention: S'=Q'.K^T (fp16 MMA), E=2^S' -> uint8 fragment-order
// gmem tile (dense uint4 stores) + fp16 register repack -> O += E.V,
// Z += rowsum(E).  Epilogue: out = O/Z; invZ stored.
// 256 threads = 8 warps, warp owns 16 q rows.  grid (CL/128, BHn).
// ---------------------------------------------------------------------------
__global__ __launch_bounds__(256) void flash_kernel(
    const __half* __restrict__ Qh, const __half* __restrict__ Kh,
    const __half* __restrict__ Vh, uint8_t* __restrict__ E8,
    float* __restrict__ invZ, float* __restrict__ out)
{
    __shared__ __half Qs[128][72];
    __shared__ __half Ks[64][72];
    __shared__ __half Vs[64][72];

    const int z = blockIdx.y, b = z >> 4, h = z & 15;
    const int qbase = blockIdx.x * 128;
    const int tid = threadIdx.x, w = tid >> 5, lane = tid & 31;
    const int g = lane >> 2, tig = lane & 3;

    const __half* Qg = Qh + ((long)b * CL + qbase) * CD + h * 64;
    #pragma unroll
    for (int j = 0; j < 4; j++) {
        int f = tid + 256 * j;
        int r = f >> 3, c = (f & 7) * 8;
        *(uint4*)&Qs[r][c] = *(const uint4*)(Qg + (long)r * CD + c);
    }
    __syncthreads();
    uint32_t aq[4][4];
    #pragma unroll
    for (int kc = 0; kc < 4; kc++)
        ldm4(aq[kc], sptr(&Qs[w * 16 + (lane & 15)][kc * 16 + (lane >> 4) * 8]));

    const __half* Kg = Kh + (long)b * CL * CD + h * 64;
    const __half* Vg = Vh + (long)b * CL * CD + h * 64;

    float acc_o[8][4];
    #pragma unroll
    for (int i = 0; i < 8; i++)
        #pragma unroll
        for (int r = 0; r < 4; r++) acc_o[i][r] = 0.f;
    float zr0 = 0.f, zr1 = 0.f;

    uint4 pk[2], pv[2];
    #pragma unroll
    for (int j = 0; j < 2; j++) {
        int f = tid + 256 * j;
        int r = f >> 3, c = (f & 7) * 8;
        pk[j] = *(const uint4*)(Kg + (long)r * CD + c);
        pv[j] = *(const uint4*)(Vg + (long)r * CD + c);
    }

    uint4* Etile = (uint4*)E8 + ((long)z * (CL / 128) + blockIdx.x) * TILE_U4;

    for (int kt = 0; kt < CL / 64; kt++) {
        #pragma unroll
        for (int j = 0; j < 2; j++) {
            int f = tid + 256 * j;
            int r = f >> 3, c = (f & 7) * 8;
            *(uint4*)&Ks[r][c] = pk[j];
            *(uint4*)&Vs[r][c] = pv[j];
        }
        __syncthreads();

        if (kt + 1 < CL / 64) {
            #pragma unroll
            for (int j = 0; j < 2; j++) {
                int f = tid + 256 * j;
                int r = f >> 3, c = (f & 7) * 8;
                long row = (long)((kt + 1) * 64 + r);
                pk[j] = *(const uint4*)(Kg + row * CD + c);
                pv[j] = *(const uint4*)(Vg + row * CD + c);
            }
        }

        float s[8][4];
        #pragma unroll
        for (int i = 0; i < 8; i++)
            #pragma unroll
            for (int r = 0; r < 4; r++) s[i][r] = 0.f;

        #pragma unroll
        for (int kc = 0; kc < 4; kc++) {
            #pragma unroll
            for (int p = 0; p < 4; p++) {
                uint32_t r4[4];
                ldm4(r4, sptr(&Ks[p * 16 + (lane & 15)][kc * 16 + (lane >> 4) * 8]));
                uint32_t b0[2] = {r4[0], r4[2]}, b1[2] = {r4[1], r4[3]};
                mma16h(s[2 * p],     aq[kc], b0);
                mma16h(s[2 * p + 1], aq[kc], b1);
            }
        }

        // 2^s, fp16 repack for PV, uint8 encode, row sums
        uint32_t ehlo[8], ehhi[8];
        uint32_t encLo[8], encHi[8];       // per-nt packed 2-byte codes
        #pragma unroll
        for (int nt = 0; nt < 8; nt++) {
            float e0 = ex2(s[nt][0]);
            float e1 = ex2(s[nt][1]);
            float e2 = ex2(s[nt][2]);
            float e3 = ex2(s[nt][3]);
            __half2 lo = __floats2half2_rn(e0, e1);
            __half2 hi = __floats2half2_rn(e2, e3);
            ehlo[nt] = *(uint32_t*)&lo;
            ehhi[nt] = *(uint32_t*)&hi;
            zr0 += e0 + e1;
            zr1 += e2 + e3;
            encLo[nt] = __byte_perm(e_enc(e0), e_enc(e1), 0x0040);
            encHi[nt] = __byte_perm(e_enc(e2), e_enc(e3), 0x0040);
        }

        // dense uint8 fragment-order stores: 2 x uint4 per thread/kt
        {
            uint4 s0, s1;
            s0.x = __byte_perm(encLo[0], encLo[1], 0x5410);
            s0.y = __byte_perm(encHi[0], encHi[1], 0x5410);
            s0.z = __byte_perm(encLo[2], encLo[3], 0x5410);
            s0.w = __byte_perm(encHi[2], encHi[3], 0x5410);
            s1.x = __byte_perm(encLo[4], encLo[5], 0x5410);
            s1.y = __byte_perm(encHi[4], encHi[5], 0x5410);
            s1.z = __byte_perm(encLo[6], encLo[7], 0x5410);
            s1.w = __byte_perm(encHi[6], encHi[7], 0x5410);
            uint4* p = Etile + (long)kt * 512 + tid;
            __stcs(p,       s0);
            __stcs(p + 256, s1);
        }

        // PV: O += E . V  (B via ldmatrix.trans on V[k][n])
        #pragma unroll
        for (int kc = 0; kc < 4; kc++) {
            uint32_t a[4] = {ehlo[2 * kc], ehhi[2 * kc], ehlo[2 * kc + 1], ehhi[2 * kc + 1]};
            #pragma unroll
            for (int p = 0; p < 4; p++) {
                uint32_t r4[4];
                ldm4t(r4, sptr(&Vs[kc * 16 + (lane & 15)][p * 16 + (lane >> 4) * 8]));
                uint32_t b0[2] = {r4[0], r4[1]}, b1[2] = {r4[2], r4[3]};
                mma16h(acc_o[2 * p],     a, b0);
                mma16h(acc_o[2 * p + 1], a, b1);
            }
        }
        __syncthreads();
    }

    zr0 += __shfl_xor_sync(0xffffffffu, zr0, 1);
    zr0 += __shfl_xor_sync(0xffffffffu, zr0, 2);
    zr1 += __shfl_xor_sync(0xffffffffu, zr1, 1);
    zr1 += __shfl_xor_sync(0xffffffffu, zr1, 2);
    const float iz0 = 1.0f / zr0;
    const float iz1 = 1.0f / zr1;
    if (tig == 0) {
        invZ[(long)z * CL + qbase + w * 16 + g]     = iz0;
        invZ[(long)z * CL + qbase + w * 16 + g + 8] = iz1;
    }
    float* Ob = out + (long)z * CL * CDK + (long)(qbase + w * 16) * CDK;
    #pragma unroll
    for (int nt = 0; nt < 8; nt++) {
        int col = nt * 8 + 2 * tig;
        *(float2*)&Ob[(long)g * CDK + col] =
            make_float2(acc_o[nt][0] * iz0, acc_o[nt][1] * iz0);
        *(float2*)&Ob[(long)(g + 8) * CDK + col] =
            make_float2(acc_o[nt][2] * iz1, acc_o[nt][3] * iz1);
    }
}

// ---------------------------------------------------------------------------
// avg from fragment-order uint8 E:
//   avg[b,q,k] = (1/16) sum_h invZ[h,q] * (ELO + enc*ESTEP)
// Decode: PRMT byte into 2^23 mantissa, subtract 2^23 per element; the ELO
// constant term is applied once per output via C = ELO * sum(W).
// grid (CL/128 ktgroups of 2, CL/128 qtiles, CB); 256 threads.
// ---------------------------------------------------------------------------
__global__ __launch_bounds__(256) void avg_kernel(const uint8_t* __restrict__ E8,
                                                  const float* __restrict__ invZ,
                                                  float* __restrict__ avg)
{
    const int b   = blockIdx.z;
    const int qt  = blockIdx.y;
    const int ktg = blockIdx.x;
    const int tid = threadIdx.x, w = tid >> 5, lane = tid & 31;
    const int g = lane >> 2, tig = lane & 3;
    const int row0 = qt * 128 + w * 16 + g;

    float W0[CH], W1[CH];
    float SW0 = 0.f, SW1 = 0.f;
    #pragma unroll
    for (int h = 0; h < CH; h++) {
        W0[h] = invZ[(long)(b * CH + h) * CL + row0]     * (1.0f / CH);
        W1[h] = invZ[(long)(b * CH + h) * CL + row0 + 8] * (1.0f / CH);
        SW0 += W0[h];
        SW1 += W1[h];
    }
    const float C0 = ELO * SW0;
    const float C1 = ELO * SW1;

    #pragma unroll
    for (int kk = 0; kk < 2; kk++) {
        const int kt = ktg * 2 + kk;
        float2 aLo[8], aHi[8];
        #pragma unroll
        for (int i = 0; i < 8; i++) {
            aLo[i] = make_float2(0.f, 0.f);
            aHi[i] = make_float2(0.f, 0.f);
        }

        #pragma unroll
        for (int h = 0; h < CH; h++) {
            const uint4* p = (const uint4*)E8
                + ((long)(b * CH + h) * (CL / 128) + qt) * TILE_U4
                + (long)kt * 512 + tid;
            const float w0 = W0[h], w1 = W1[h];
            #pragma unroll
            for (int jj = 0; jj < 2; jj++) {
                uint4 u = __ldcs(p + jj * 256);
                const int nb = 4 * jj;
                // u.x: row g, nt=nb..nb+1 ; u.y: row g+8, nt=nb..nb+1
                // u.z: row g, nt=nb+2..nb+3 ; u.w: row g+8, nt=nb+2..nb+3
                #pragma unroll
                for (int k = 0; k < 4; k++) {
                    const int nt  = nb + (k >> 1);
                    const int nt2 = nb + 2 + (k >> 1);
                    float fx = __uint_as_float(__byte_perm(u.x, 0x4B000000u, 0x7440 + k));
                    float fy = __uint_as_float(__byte_perm(u.y, 0x4B000000u, 0x7440 + k));
                    float fz = __uint_as_float(__byte_perm(u.z, 0x4B000000u, 0x7440 + k));
                    float fw = __uint_as_float(__byte_perm(u.w, 0x4B000000u, 0x7440 + k));
                    float* dLo  = (k & 1) ? &aLo[nt].y  : &aLo[nt].x;
                    float* dHi  = (k & 1) ? &aHi[nt].y  : &aHi[nt].x;
                    float* dLo2 = (k & 1) ? &aLo[nt2].y : &aLo[nt2].x;
                    float* dHi2 = (k & 1) ? &aHi[nt2].y : &aHi[nt2].x;
                    *dLo  = fmaf(w0, fx - EMAGIC, *dLo);
                    *dHi  = fmaf(w1, fy - EMAGIC, *dHi);
                    *dLo2 = fmaf(w0, fz - EMAGIC, *dLo2);
                    *dHi2 = fmaf(w1, fw - EMAGIC, *dHi2);
                }
            }
        }

        float* A0 = avg + ((long)b * CL + row0) * CL;
        #pragma unroll
        for (int nt = 0; nt < 8; nt++) {
            int col = kt * 64 + nt * 8 + 2 * tig;
            *(float2*)&A0[col] =
                make_float2(fmaf(ESTEP, aLo[nt].x, C0), fmaf(ESTEP, aLo[nt].y, C0));
            *(float2*)&A0[8L * CL + col] =
                make_float2(fmaf(ESTEP, aHi[nt].x, C1), fmaf(ESTEP, aHi[nt].y, C1));
        }
    }
}

// ---------------------------------------------------------------------------
extern "C" void kernel_launch(void* const* d_in, const int* in_sizes, int n_in,
                              void* d_out, int out_size)
{
    const float* q  = (const float*)d_in[0];
    const float* k  = (const float*)d_in[1];
    const float* v  = (const float*)d_in[2];
    const float* wq = (const float*)d_in[3];
    const float* wk = (const float*)d_in[4];
    const float* wv = (const float*)d_in[5];

    float* out = (float*)d_out;                        // [B,H,L,64]
    float* avg = out + (long)CB * CH * CL * CDK;       // [B,L,L]

    float   *iZ;
    __half  *Xh, *Wh, *Qh, *Kh, *Vh;
    uint8_t *Ep;
    cudaGetSymbolAddress((void**)&Xh, g_Xh);
    cudaGetSymbolAddress((void**)&Wh, g_Wh);
    cudaGetSymbolAddress((void**)&Qh, g_Qh);
    cudaGetSymbolAddress((void**)&Kh, g_Kh);
    cudaGetSymbolAddress((void**)&Vh, g_Vh);
    cudaGetSymbolAddress((void**)&Ep, g_E8);
    cudaGetSymbolAddress((void**)&iZ, g_invZ);

    // 0) fp32 -> fp16 conversion of all GEMM operands
    dim3 cg(PROJ_ELEMS / (256 * 8), 6);
    cvt_kernel<<<cg, 256>>>(q, k, v, wq, wk, wv, Xh, Wh);

    // 1) Projections + fused per-head L2 norm (BM=128, BN=128, BK=64)
    dim3 pg(CD / 128, (CB * CL) / 128, 3);
    proj_norm_kernel<<<pg, 256>>>(Xh, Wh, Qh, Kh, Vh);

    // 2) Fused attention: fragment-order uint8 E + invZ + out
    dim3 fg(CL / 128, BHn);
    flash_kernel<<<fg, 256>>>(Qh, Kh, Vh, Ep, iZ, out);

    // 3) attn_avg from fragment-order uint8 E
    dim3 ag(CL / 128, CL / 128, CB);
    avg_kernel<<<ag, 256>>>(Ep, iZ, avg);
}

// round 16
// speedup vs baseline: 1.4794x; 1.0107x over previous
#include <cuda_runtime.h>
#include <cuda_fp16.h>
#include <stdint.h>

// Problem constants
#define CB 2
#define CL 2048
#define CD 1024
#define CH 16
#define CDK 64

constexpr int  BHn        = CB * CH;               // 32
constexpr long PROJ_ELEMS = (long)CB * CL * CD;    // 4,194,304
constexpr long W_ELEMS    = (long)CD * CD;         // 1,048,576
constexpr long S_ELEMS    = (long)BHn * CL * CL;   // 134,217,728
constexpr long ZN         = (long)BHn * CL;        // 65,536
constexpr long TILE_U4    = 16384;                 // uint4 per 128x2048 uint8 E tile

// Q gets 1/sqrt(64) * log2(e) folded into its normalization
#define QCOEF 0.18033688011112042f

// uint8 E encoding: e = 2^s', s' in +-0.1803 -> e in [0.8824, 1.1335]
#define ELO    0.87f
#define EINV   910.7142857f        // 255 / 0.28
#define ESTEP  0.001098039216f     // 0.28 / 255
#define EMAGIC 8388608.0f          // 2^23

// Scratch (static device globals -- no runtime allocation)
__device__ __half  g_Xh[3 * PROJ_ELEMS];           // q,k,v inputs, fp16
__device__ __half  g_Wh[3 * W_ELEMS];              // wq,wk,wv weights, fp16
__device__ __half  g_Qh[PROJ_ELEMS];               // normalized Q * QCOEF, fp16
__device__ __half  g_Kh[PROJ_ELEMS];               // normalized K, fp16
__device__ __half  g_Vh[PROJ_ELEMS];               // V projection, fp16
__device__ uint8_t g_E8[S_ELEMS];                  // exp(scores), uint8, fragment order
__device__ float   g_invZ[ZN];

// ---------------------------------------------------------------------------
// helpers
// ---------------------------------------------------------------------------
__device__ __forceinline__ void mma16h(float* d, const uint32_t* a, const uint32_t* b) {
    asm volatile(
        "mma.sync.aligned.m16n8k16.row.col.f32.f16.f16.f32 "
        "{%0,%1,%2,%3}, {%4,%5,%6,%7}, {%8,%9}, {%0,%1,%2,%3};"
        : "+f"(d[0]), "+f"(d[1]), "+f"(d[2]), "+f"(d[3])
        : "r"(a[0]), "r"(a[1]), "r"(a[2]), "r"(a[3]), "r"(b[0]), "r"(b[1]));
}

__device__ __forceinline__ uint32_t sptr(const void* p) {
    return (uint32_t)__cvta_generic_to_shared(p);
}

__device__ __forceinline__ void ldm4(uint32_t* a, uint32_t addr) {
    asm volatile("ldmatrix.sync.aligned.m8n8.x4.shared.b16 {%0,%1,%2,%3}, [%4];"
                 : "=r"(a[0]), "=r"(a[1]), "=r"(a[2]), "=r"(a[3]) : "r"(addr));
}

__device__ __forceinline__ void ldm4t(uint32_t* a, uint32_t addr) {
    asm volatile("ldmatrix.sync.aligned.m8n8.x4.trans.shared.b16 {%0,%1,%2,%3}, [%4];"
                 : "=r"(a[0]), "=r"(a[1]), "=r"(a[2]), "=r"(a[3]) : "r"(addr));
}

__device__ __forceinline__ float ex2(float x) {
    float y;
    asm("ex2.approx.f32 %0, %1;" : "=f"(y) : "f"(x));
    return y;
}

__device__ __forceinline__ uint32_t e_enc(float e) {
    return __float_as_uint(fmaf(e - ELO, EINV, EMAGIC));
}

// ---------------------------------------------------------------------------
// fp32 -> fp16 conversion: z=0..2 inputs (4M elems), z=3..5 weights (1M).
// ---------------------------------------------------------------------------
__global__ __launch_bounds__(256) void cvt_kernel(
    const float* __restrict__ q, const float* __restrict__ k,
    const float* __restrict__ v,
    const float* __restrict__ wq, const float* __restrict__ wk,
    const float* __restrict__ wv,
    __half* __restrict__ Xh, __half* __restrict__ Wh)
{
    const int z = blockIdx.y;
    const float* src = (z == 0) ? q : (z == 1) ? k : (z == 2) ? v
                     : (z == 3) ? wq : (z == 4) ? wk : wv;
    const long n = (z < 3) ? PROJ_ELEMS : W_ELEMS;
    __half* dst = (z < 3) ? Xh + (long)z * PROJ_ELEMS
                          : Wh + (long)(z - 3) * W_ELEMS;
    const long i = ((long)blockIdx.x * 256 + threadIdx.x) * 8;
    if (i < n) {
        float4 a = *(const float4*)(src + i);
        float4 b = *(const float4*)(src + i + 4);
        __half2 h[4] = {__floats2half2_rn(a.x, a.y), __floats2half2_rn(a.z, a.w),
                        __floats2half2_rn(b.x, b.y), __floats2half2_rn(b.z, b.w)};
        *(uint4*)(dst + i) = *(uint4*)h;
    }
}

// ---------------------------------------------------------------------------
// Fused projection + per-head L2 norm, all-fp16 data path.
// BM=128, BN=128, BK=64, 256 threads as 4x2 warps.  (validated round 14)
// ---------------------------------------------------------------------------
__global__ __launch_bounds__(256) void proj_norm_kernel(
    const __half* __restrict__ Xh, const __half* __restrict__ Wh,
    __half* __restrict__ Qo, __half* __restrict__ Ko, __half* __restrict__ Vo)
{
    __shared__ __half As[128][72];
    __shared__ __half Bs[128][72];

    const int z = blockIdx.z;
    const __half* Ab = Xh + (long)z * PROJ_ELEMS + (long)blockIdx.y * 128 * CD;
    const __half* Bb = Wh + (long)z * W_ELEMS   + (long)blockIdx.x * 128 * CD;
    __half*       C  = (z == 0) ? Qo : (z == 1) ? Ko : Vo;
    const bool  donorm = (z < 2);
    const float coef   = (z == 0) ? QCOEF : 1.0f;

    const int tid  = threadIdx.x;
    const int w    = tid >> 5, lane = tid & 31;
    const int wm   = w >> 1, wn = w & 1;
    const int g    = lane >> 2, tig = lane & 3;

    float acc[2][8][4];
    #pragma unroll
    for (int i = 0; i < 2; i++)
        #pragma unroll
        for (int j = 0; j < 8; j++)
            #pragma unroll
            for (int r = 0; r < 4; r++) acc[i][j][r] = 0.f;

    uint4 pa[4], pb[4];
    #pragma unroll
    for (int j = 0; j < 4; j++) {
        int s = tid + 256 * j;
        pa[j] = *(const uint4*)(Ab + (long)(s >> 3) * CD + (s & 7) * 8);
        pb[j] = *(const uint4*)(Bb + (long)(s >> 3) * CD + (s & 7) * 8);
    }

    for (int k0 = 0; k0 < CD; k0 += 64) {
        #pragma unroll
        for (int j = 0; j < 4; j++) {
            int s = tid + 256 * j;
            *(uint4*)&As[s >> 3][(s & 7) * 8] = pa[j];
            *(uint4*)&Bs[s >> 3][(s & 7) * 8] = pb[j];
        }
        __syncthreads();

        if (k0 + 64 < CD) {
            #pragma unroll
            for (int j = 0; j < 4; j++) {
                int s = tid + 256 * j;
                pa[j] = *(const uint4*)(Ab + (long)(s >> 3) * CD + k0 + 64 + (s & 7) * 8);
                pb[j] = *(const uint4*)(Bb + (long)(s >> 3) * CD + k0 + 64 + (s & 7) * 8);
            }
        }

        #pragma unroll
        for (int ks = 0; ks < 4; ks++) {
            const int c0 = ks * 16;
            uint32_t af[2][4], bf[8][2];
            #pragma unroll
            for (int mt = 0; mt < 2; mt++)
                ldm4(af[mt], sptr(&As[wm * 32 + mt * 16 + (lane & 15)][c0 + (lane >> 4) * 8]));
            #pragma unroll
            for (int nh = 0; nh < 4; nh++) {
                uint32_t r4[4];
                ldm4(r4, sptr(&Bs[wn * 64 + nh * 16 + (lane & 15)][c0 + (lane >> 4) * 8]));
                bf[2 * nh][0]     = r4[0]; bf[2 * nh][1]     = r4[2];
                bf[2 * nh + 1][0] = r4[1]; bf[2 * nh + 1][1] = r4[3];
            }
            #pragma unroll
            for (int mt = 0; mt < 2; mt++)
                #pragma unroll
                for (int nt = 0; nt < 8; nt++)
                    mma16h(acc[mt][nt], af[mt], bf[nt]);
        }
        __syncthreads();
    }

    float sc[2][2] = {{1.f, 1.f}, {1.f, 1.f}};
    if (donorm) {
        #pragma unroll
        for (int mt = 0; mt < 2; mt++) {
            float sA = 0.f, sB = 0.f;
            #pragma unroll
            for (int nt = 0; nt < 8; nt++) {
                sA += acc[mt][nt][0] * acc[mt][nt][0] + acc[mt][nt][1] * acc[mt][nt][1];
                sB += acc[mt][nt][2] * acc[mt][nt][2] + acc[mt][nt][3] * acc[mt][nt][3];
            }
            #pragma unroll
            for (int o = 1; o <= 2; o <<= 1) {
                sA += __shfl_xor_sync(0xffffffffu, sA, o);
                sB += __shfl_xor_sync(0xffffffffu, sB, o);
            }
            sc[mt][0] = coef / fmaxf(sqrtf(sA), 1e-12f);
            sc[mt][1] = coef / fmaxf(sqrtf(sB), 1e-12f);
        }
    }

    __half* Cb = C + (long)blockIdx.y * 128 * CD + (long)blockIdx.x * 128;
    #pragma unroll
    for (int mt = 0; mt < 2; mt++)
        #pragma unroll
        for (int nt = 0; nt < 8; nt++) {
            long r0  = wm * 32 + mt * 16 + g;
            int  col = wn * 64 + nt * 8 + 2 * tig;
            *(__half2*)&Cb[r0 * CD + col] =
                __floats2half2_rn(acc[mt][nt][0] * sc[mt][0],
                                  acc[mt][nt][1] * sc[mt][0]);
            *(__half2*)&Cb[(r0 + 8) * CD + col] =
                __floats2half2_rn(acc[mt][nt][2] * sc[mt][1],
                                  acc[mt][nt][3] * sc[mt][1]);
        }
}

// ---------------------------------------------------------------------------
// Fused flash attention, per-K-block pipelined (register-lean):
// per kt, for each K block p: 8 score MMAs -> ex2 -> pack -> 8 PV MMAs
// (p is PV's k-block), enc codes collected for one dense uint4-pair store.
// Accumulation order identical to round 15 (bit-exact).
// 256 threads = 8 warps, warp owns 16 q rows.  grid (CL/128, BHn), 2 CTA/SM.
// ---------------------------------------------------------------------------
__global__ __launch_bounds__(256, 2) void flash_kernel(
    const __half* __restrict__ Qh, const __half* __restrict__ Kh,
    const __half* __restrict__ Vh, uint8_t* __restrict__ E8,
    float* __restrict__ invZ, float* __restrict__ out)
{
    __shared__ __half Qs[128][72];
    __shared__ __half Ks[64][72];
    __shared__ __half Vs[64][72];

    const int z = blockIdx.y, b = z >> 4, h = z & 15;
    const int qbase = blockIdx.x * 128;
    const int tid = threadIdx.x, w = tid >> 5, lane = tid & 31;
    const int g = lane >> 2, tig = lane & 3;

    const __half* Qg = Qh + ((long)b * CL + qbase) * CD + h * 64;
    #pragma unroll
    for (int j = 0; j < 4; j++) {
        int f = tid + 256 * j;
        int r = f >> 3, c = (f & 7) * 8;
        *(uint4*)&Qs[r][c] = *(const uint4*)(Qg + (long)r * CD + c);
    }
    __syncthreads();
    uint32_t aq[4][4];
    #pragma unroll
    for (int kc = 0; kc < 4; kc++)
        ldm4(aq[kc], sptr(&Qs[w * 16 + (lane & 15)][kc * 16 + (lane >> 4) * 8]));

    const __half* Kg = Kh + (long)b * CL * CD + h * 64;
    const __half* Vg = Vh + (long)b * CL * CD + h * 64;

    float acc_o[8][4];
    #pragma unroll
    for (int i = 0; i < 8; i++)
        #pragma unroll
        for (int r = 0; r < 4; r++) acc_o[i][r] = 0.f;
    float zr0 = 0.f, zr1 = 0.f;

    uint4 pk[2], pv[2];
    #pragma unroll
    for (int j = 0; j < 2; j++) {
        int f = tid + 256 * j;
        int r = f >> 3, c = (f & 7) * 8;
        pk[j] = *(const uint4*)(Kg + (long)r * CD + c);
        pv[j] = *(const uint4*)(Vg + (long)r * CD + c);
    }

    uint4* Etile = (uint4*)E8 + ((long)z * (CL / 128) + blockIdx.x) * TILE_U4;

    for (int kt = 0; kt < CL / 64; kt++) {
        #pragma unroll
        for (int j = 0; j < 2; j++) {
            int f = tid + 256 * j;
            int r = f >> 3, c = (f & 7) * 8;
            *(uint4*)&Ks[r][c] = pk[j];
            *(uint4*)&Vs[r][c] = pv[j];
        }
        __syncthreads();

        if (kt + 1 < CL / 64) {
            #pragma unroll
            for (int j = 0; j < 2; j++) {
                int f = tid + 256 * j;
                int r = f >> 3, c = (f & 7) * 8;
                long row = (long)((kt + 1) * 64 + r);
                pk[j] = *(const uint4*)(Kg + row * CD + c);
                pv[j] = *(const uint4*)(Vg + row * CD + c);
            }
        }

        uint32_t encLo[8], encHi[8];
        #pragma unroll
        for (int p = 0; p < 4; p++) {
            // scores for K block p (nt = 2p, 2p+1)
            float s0[4] = {0.f, 0.f, 0.f, 0.f};
            float s1[4] = {0.f, 0.f, 0.f, 0.f};
            #pragma unroll
            for (int kc = 0; kc < 4; kc++) {
                uint32_t r4[4];
                ldm4(r4, sptr(&Ks[p * 16 + (lane & 15)][kc * 16 + (lane >> 4) * 8]));
                uint32_t b0[2] = {r4[0], r4[2]}, b1[2] = {r4[1], r4[3]};
                mma16h(s0, aq[kc], b0);
                mma16h(s1, aq[kc], b1);
            }
            // exp + pack + encode (order matches round 15: nt=2p then 2p+1)
            float e0 = ex2(s0[0]), e1 = ex2(s0[1]), e2 = ex2(s0[2]), e3 = ex2(s0[3]);
            float f0 = ex2(s1[0]), f1 = ex2(s1[1]), f2 = ex2(s1[2]), f3 = ex2(s1[3]);
            __half2 lo0 = __floats2half2_rn(e0, e1);
            __half2 hi0 = __floats2half2_rn(e2, e3);
            __half2 lo1 = __floats2half2_rn(f0, f1);
            __half2 hi1 = __floats2half2_rn(f2, f3);
            zr0 += e0 + e1;  zr1 += e2 + e3;
            zr0 += f0 + f1;  zr1 += f2 + f3;
            encLo[2 * p]     = __byte_perm(e_enc(e0), e_enc(e1), 0x0040);
            encHi[2 * p]     = __byte_perm(e_enc(e2), e_enc(e3), 0x0040);
            encLo[2 * p + 1] = __byte_perm(e_enc(f0), e_enc(f1), 0x0040);
            encHi[2 * p + 1] = __byte_perm(e_enc(f2), e_enc(f3), 0x0040);

            // PV: this score block is PV's k-block p
            uint32_t a[4] = {*(uint32_t*)&lo0, *(uint32_t*)&hi0,
                             *(uint32_t*)&lo1, *(uint32_t*)&hi1};
            #pragma unroll
            for (int pp = 0; pp < 4; pp++) {
                uint32_t r4[4];
                ldm4t(r4, sptr(&Vs[p * 16 + (lane & 15)][pp * 16 + (lane >> 4) * 8]));
                uint32_t b0[2] = {r4[0], r4[1]}, b1[2] = {r4[2], r4[3]};
                mma16h(acc_o[2 * pp],     a, b0);
                mma16h(acc_o[2 * pp + 1], a, b1);
            }
        }

        // dense uint8 fragment-order stores: 2 x uint4 per thread/kt
        {
            uint4 s0, s1;
            s0.x = __byte_perm(encLo[0], encLo[1], 0x5410);
            s0.y = __byte_perm(encHi[0], encHi[1], 0x5410);
            s0.z = __byte_perm(encLo[2], encLo[3], 0x5410);
            s0.w = __byte_perm(encHi[2], encHi[3], 0x5410);
            s1.x = __byte_perm(encLo[4], encLo[5], 0x5410);
            s1.y = __byte_perm(encHi[4], encHi[5], 0x5410);
            s1.z = __byte_perm(encLo[6], encLo[7], 0x5410);
            s1.w = __byte_perm(encHi[6], encHi[7], 0x5410);
            uint4* p = Etile + (long)kt * 512 + tid;
            __stcs(p,       s0);
            __stcs(p + 256, s1);
        }
        __syncthreads();
    }

    zr0 += __shfl_xor_sync(0xffffffffu, zr0, 1);
    zr0 += __shfl_xor_sync(0xffffffffu, zr0, 2);
    zr1 += __shfl_xor_sync(0xffffffffu, zr1, 1);
    zr1 += __shfl_xor_sync(0xffffffffu, zr1, 2);
    const float iz0 = 1.0f / zr0;
    const float iz1 = 1.0f / zr1;
    if (tig == 0) {
        invZ[(long)z * CL + qbase + w * 16 + g]     = iz0;
        invZ[(long)z * CL + qbase + w * 16 + g + 8] = iz1;
    }
    float* Ob = out + (long)z * CL * CDK + (long)(qbase + w * 16) * CDK;
    #pragma unroll
    for (int nt = 0; nt < 8; nt++) {
        int col = nt * 8 + 2 * tig;
        *(float2*)&Ob[(long)g * CDK + col] =
            make_float2(acc_o[nt][0] * iz0, acc_o[nt][1] * iz0);
        *(float2*)&Ob[(long)(g + 8) * CDK + col] =
            make_float2(acc_o[nt][2] * iz1, acc_o[nt][3] * iz1);
    }
}

// ---------------------------------------------------------------------------
// avg from fragment-order uint8 E (weights in smem; 2 CTA/SM):
//   avg[b,q,k] = (1/16) sum_h invZ[h,q] * (ELO + enc*ESTEP)
// grid (CL/128 ktgroups of 2, CL/128 qtiles, CB); 256 threads.
// ---------------------------------------------------------------------------
__global__ __launch_bounds__(256, 2) void avg_kernel(const uint8_t* __restrict__ E8,
                                                     const float* __restrict__ invZ,
                                                     float* __restrict__ avg)
{
    __shared__ float Wsm[128][17];     // [row within qtile][head]

    const int b   = blockIdx.z;
    const int qt  = blockIdx.y;
    const int ktg = blockIdx.x;
    const int tid = threadIdx.x, w = tid >> 5, lane = tid & 31;
    const int g = lane >> 2, tig = lane & 3;
    const int rA = w * 16 + g;         // local row (0..127), and rA+8
    const int row0 = qt * 128 + rA;

    // cooperative load of all 128x16 weights
    for (int i = tid; i < 128 * CH; i += 256) {
        int r = i >> 4, h = i & 15;
        Wsm[r][h] = invZ[(long)(b * CH + h) * CL + qt * 128 + r] * (1.0f / CH);
    }
    __syncthreads();

    float SW0 = 0.f, SW1 = 0.f;
    #pragma unroll
    for (int h = 0; h < CH; h++) {
        SW0 += Wsm[rA][h];
        SW1 += Wsm[rA + 8][h];
    }
    const float C0 = ELO * SW0;
    const float C1 = ELO * SW1;

    #pragma unroll
    for (int kk = 0; kk < 2; kk++) {
        const int kt = ktg * 2 + kk;
        float2 aLo[8], aHi[8];
        #pragma unroll
        for (int i = 0; i < 8; i++) {
            aLo[i] = make_float2(0.f, 0.f);
            aHi[i] = make_float2(0.f, 0.f);
        }

        #pragma unroll
        for (int h = 0; h < CH; h++) {
            const uint4* p = (const uint4*)E8
                + ((long)(b * CH + h) * (CL / 128) + qt) * TILE_U4
                + (long)kt * 512 + tid;
            const float w0 = Wsm[rA][h], w1 = Wsm[rA + 8][h];
            #pragma unroll
            for (int jj = 0; jj < 2; jj++) {
                uint4 u = __ldcs(p + jj * 256);
                const int nb = 4 * jj;
                #pragma unroll
                for (int k = 0; k < 4; k++) {
                    const int nt  = nb + (k >> 1);
                    const int nt2 = nb + 2 + (k >> 1);
                    float fx = __uint_as_float(__byte_perm(u.x, 0x4B000000u, 0x7440 + k));
                    float fy = __uint_as_float(__byte_perm(u.y, 0x4B000000u, 0x7440 + k));
                    float fz = __uint_as_float(__byte_perm(u.z, 0x4B000000u, 0x7440 + k));
                    float fw = __uint_as_float(__byte_perm(u.w, 0x4B000000u, 0x7440 + k));
                    float* dLo  = (k & 1) ? &aLo[nt].y  : &aLo[nt].x;
                    float* dHi  = (k & 1) ? &aHi[nt].y  : &aHi[nt].x;
                    float* dLo2 = (k & 1) ? &aLo[nt2].y : &aLo[nt2].x;
                    float* dHi2 = (k & 1) ? &aHi[nt2].y : &aHi[nt2].x;
                    *dLo  = fmaf(w0, fx - EMAGIC, *dLo);
                    *dHi  = fmaf(w1, fy - EMAGIC, *dHi);
                    *dLo2 = fmaf(w0, fz - EMAGIC, *dLo2);
                    *dHi2 = fmaf(w1, fw - EMAGIC, *dHi2);
                }
            }
        }

        float* A0 = avg + ((long)b * CL + row0) * CL;
        #pragma unroll
        for (int nt = 0; nt < 8; nt++) {
            int col = kt * 64 + nt * 8 + 2 * tig;
            *(float2*)&A0[col] =
                make_float2(fmaf(ESTEP, aLo[nt].x, C0), fmaf(ESTEP, aLo[nt].y, C0));
            *(float2*)&A0[8L * CL + col] =
                make_float2(fmaf(ESTEP, aHi[nt].x, C1), fmaf(ESTEP, aHi[nt].y, C1));
        }
    }
}

// ---------------------------------------------------------------------------
extern "C" void kernel_launch(void* const* d_in, const int* in_sizes, int n_in,
                              void* d_out, int out_size)
{
    const float* q  = (const float*)d_in[0];
    const float* k  = (const float*)d_in[1];
    const float* v  = (const float*)d_in[2];
    const float* wq = (const float*)d_in[3];
    const float* wk = (const float*)d_in[4];
    const float* wv = (const float*)d_in[5];

    float* out = (float*)d_out;                        // [B,H,L,64]
    float* avg = out + (long)CB * CH * CL * CDK;       // [B,L,L]

    float   *iZ;
    __half  *Xh, *Wh, *Qh, *Kh, *Vh;
    uint8_t *Ep;
    cudaGetSymbolAddress((void**)&Xh, g_Xh);
    cudaGetSymbolAddress((void**)&Wh, g_Wh);
    cudaGetSymbolAddress((void**)&Qh, g_Qh);
    cudaGetSymbolAddress((void**)&Kh, g_Kh);
    cudaGetSymbolAddress((void**)&Vh, g_Vh);
    cudaGetSymbolAddress((void**)&Ep, g_E8);
    cudaGetSymbolAddress((void**)&iZ, g_invZ);

    // 0) fp32 -> fp16 conversion of all GEMM operands
    dim3 cg(PROJ_ELEMS / (256 * 8), 6);
    cvt_kernel<<<cg, 256>>>(q, k, v, wq, wk, wv, Xh, Wh);

    // 1) Projections + fused per-head L2 norm (BM=128, BN=128, BK=64)
    dim3 pg(CD / 128, (CB * CL) / 128, 3);
    proj_norm_kernel<<<pg, 256>>>(Xh, Wh, Qh, Kh, Vh);

    // 2) Fused attention: fragment-order uint8 E + invZ + out
    dim3 fg(CL / 128, BHn);
    flash_kernel<<<fg, 256>>>(Qh, Kh, Vh, Ep, iZ, out);

    // 3) attn_avg from fragment-order uint8 E
    dim3 ag(CL / 128, CL / 128, CB);
    avg_kernel<<<ag, 256>>>(Ep, iZ, avg);
}

// round 17
// speedup vs baseline: 1.5077x; 1.0191x over previous
#include <cuda_runtime.h>
#include <cuda_fp16.h>
#include <stdint.h>

// Problem constants
#define CB 2
#define CL 2048
#define CD 1024
#define CH 16
#define CDK 64

constexpr int  BHn        = CB * CH;               // 32
constexpr long PROJ_ELEMS = (long)CB * CL * CD;    // 4,194,304
constexpr long W_ELEMS    = (long)CD * CD;         // 1,048,576
constexpr long S_ELEMS    = (long)BHn * CL * CL;   // 134,217,728
constexpr long ZN         = (long)BHn * CL;        // 65,536
constexpr long TILE_U4    = 16384;                 // uint4 per 128x2048 uint8 E tile

// Q gets 1/sqrt(64) * log2(e) folded into its normalization
#define QCOEF 0.18033688011112042f

// uint8 E encoding: e = 2^s', s' in +-0.1803 -> e in [0.8824, 1.1335]
#define ELO    0.87f
#define EINV   910.7142857f        // 255 / 0.28
#define ESTEP  0.001098039216f     // 0.28 / 255
#define EMAGIC 8388608.0f          // 2^23

// proj double-buffer geometry (halves)
constexpr int PROW = 72;                            // padded row (halves)
constexpr int PBUF = 2 * 128 * PROW;                // A+B per buffer = 18432 halves
constexpr int PSMEM_BYTES = 2 * PBUF * 2;           // 73728 bytes

// Scratch (static device globals -- no runtime allocation)
__device__ __half  g_Xh[3 * PROJ_ELEMS];           // q,k,v inputs, fp16
__device__ __half  g_Wh[3 * W_ELEMS];              // wq,wk,wv weights, fp16
__device__ __half  g_Qh[PROJ_ELEMS];               // normalized Q * QCOEF, fp16
__device__ __half  g_Kh[PROJ_ELEMS];               // normalized K, fp16
__device__ __half  g_Vh[PROJ_ELEMS];               // V projection, fp16
__device__ uint8_t g_E8[S_ELEMS];                  // exp(scores), uint8, fragment order
__device__ float   g_invZ[ZN];

// ---------------------------------------------------------------------------
// helpers
// ---------------------------------------------------------------------------
__device__ __forceinline__ void mma16h(float* d, const uint32_t* a, const uint32_t* b) {
    asm volatile(
        "mma.sync.aligned.m16n8k16.row.col.f32.f16.f16.f32 "
        "{%0,%1,%2,%3}, {%4,%5,%6,%7}, {%8,%9}, {%0,%1,%2,%3};"
        : "+f"(d[0]), "+f"(d[1]), "+f"(d[2]), "+f"(d[3])
        : "r"(a[0]), "r"(a[1]), "r"(a[2]), "r"(a[3]), "r"(b[0]), "r"(b[1]));
}

__device__ __forceinline__ uint32_t sptr(const void* p) {
    return (uint32_t)__cvta_generic_to_shared(p);
}

__device__ __forceinline__ void ldm4(uint32_t* a, uint32_t addr) {
    asm volatile("ldmatrix.sync.aligned.m8n8.x4.shared.b16 {%0,%1,%2,%3}, [%4];"
                 : "=r"(a[0]), "=r"(a[1]), "=r"(a[2]), "=r"(a[3]) : "r"(addr));
}

__device__ __forceinline__ void ldm4t(uint32_t* a, uint32_t addr) {
    asm volatile("ldmatrix.sync.aligned.m8n8.x4.trans.shared.b16 {%0,%1,%2,%3}, [%4];"
                 : "=r"(a[0]), "=r"(a[1]), "=r"(a[2]), "=r"(a[3]) : "r"(addr));
}

__device__ __forceinline__ float ex2(float x) {
    float y;
    asm("ex2.approx.f32 %0, %1;" : "=f"(y) : "f"(x));
    return y;
}

__device__ __forceinline__ uint32_t e_enc(float e) {
    return __float_as_uint(fmaf(e - ELO, EINV, EMAGIC));
}

__device__ __forceinline__ void cpa16(uint32_t dst, const void* src) {
    asm volatile("cp.async.cg.shared.global [%0], [%1], 16;" :: "r"(dst), "l"(src));
}
__device__ __forceinline__ void cpa_commit() {
    asm volatile("cp.async.commit_group;");
}
template<int N>
__device__ __forceinline__ void cpa_wait() {
    asm volatile("cp.async.wait_group %0;" :: "n"(N));
}

// ---------------------------------------------------------------------------
// fp32 -> fp16 conversion: z=0..2 inputs (4M elems), z=3..5 weights (1M).
// ---------------------------------------------------------------------------
__global__ __launch_bounds__(256) void cvt_kernel(
    const float* __restrict__ q, const float* __restrict__ k,
    const float* __restrict__ v,
    const float* __restrict__ wq, const float* __restrict__ wk,
    const float* __restrict__ wv,
    __half* __restrict__ Xh, __half* __restrict__ Wh)
{
    const int z = blockIdx.y;
    const float* src = (z == 0) ? q : (z == 1) ? k : (z == 2) ? v
                     : (z == 3) ? wq : (z == 4) ? wk : wv;
    const long n = (z < 3) ? PROJ_ELEMS : W_ELEMS;
    __half* dst = (z < 3) ? Xh + (long)z * PROJ_ELEMS
                          : Wh + (long)(z - 3) * W_ELEMS;
    const long i = ((long)blockIdx.x * 256 + threadIdx.x) * 8;
    if (i < n) {
        float4 a = *(const float4*)(src + i);
        float4 b = *(const float4*)(src + i + 4);
        __half2 h[4] = {__floats2half2_rn(a.x, a.y), __floats2half2_rn(a.z, a.w),
                        __floats2half2_rn(b.x, b.y), __floats2half2_rn(b.z, b.w)};
        *(uint4*)(dst + i) = *(uint4*)h;
    }
}

// ---------------------------------------------------------------------------
// Fused projection + per-head L2 norm, cp.async double-buffered pipeline.
// BM=128, BN=128, BK=64, 256 threads as 4x2 warps; dynamic smem 72KB.
// Compute / fragment order identical to round 14-16 (bit-exact results).
// ---------------------------------------------------------------------------
__global__ __launch_bounds__(256) void proj_norm_kernel(
    const __half* __restrict__ Xh, const __half* __restrict__ Wh,
    __half* __restrict__ Qo, __half* __restrict__ Ko, __half* __restrict__ Vo)
{
    extern __shared__ __half sm[];

    const int z = blockIdx.z;
    const __half* Ab = Xh + (long)z * PROJ_ELEMS + (long)blockIdx.y * 128 * CD;
    const __half* Bb = Wh + (long)z * W_ELEMS   + (long)blockIdx.x * 128 * CD;
    __half*       C  = (z == 0) ? Qo : (z == 1) ? Ko : Vo;
    const bool  donorm = (z < 2);
    const float coef   = (z == 0) ? QCOEF : 1.0f;

    const int tid  = threadIdx.x;
    const int w    = tid >> 5, lane = tid & 31;
    const int wm   = w >> 1, wn = w & 1;
    const int g    = lane >> 2, tig = lane & 3;

    float acc[2][8][4];
    #pragma unroll
    for (int i = 0; i < 2; i++)
        #pragma unroll
        for (int j = 0; j < 8; j++)
            #pragma unroll
            for (int r = 0; r < 4; r++) acc[i][j][r] = 0.f;

    // issue tile 0 into buffer 0
    #pragma unroll
    for (int j = 0; j < 4; j++) {
        int s = tid + 256 * j;
        int r = s >> 3, c = (s & 7) * 8;
        cpa16(sptr(sm + (long)r * PROW + c), Ab + (long)r * CD + c);
        cpa16(sptr(sm + 128 * PROW + (long)r * PROW + c), Bb + (long)r * CD + c);
    }
    cpa_commit();

    int buf = 0;
    for (int k0 = 0; k0 < CD; k0 += 64) {
        // prefetch next tile into the other buffer (no registers consumed)
        if (k0 + 64 < CD) {
            __half* As1 = sm + (buf ^ 1) * PBUF;
            __half* Bs1 = As1 + 128 * PROW;
            #pragma unroll
            for (int j = 0; j < 4; j++) {
                int s = tid + 256 * j;
                int r = s >> 3, c = (s & 7) * 8;
                cpa16(sptr(As1 + (long)r * PROW + c), Ab + (long)r * CD + k0 + 64 + c);
                cpa16(sptr(Bs1 + (long)r * PROW + c), Bb + (long)r * CD + k0 + 64 + c);
            }
            cpa_commit();
            cpa_wait<1>();      // current tile's group complete
        } else {
            cpa_wait<0>();
        }
        __syncthreads();

        __half* As = sm + buf * PBUF;
        __half* Bs = As + 128 * PROW;

        #pragma unroll
        for (int ks = 0; ks < 4; ks++) {
            const int c0 = ks * 16;
            uint32_t af[2][4], bf[8][2];
            #pragma unroll
            for (int mt = 0; mt < 2; mt++)
                ldm4(af[mt], sptr(As + (long)(wm * 32 + mt * 16 + (lane & 15)) * PROW
                                     + c0 + (lane >> 4) * 8));
            #pragma unroll
            for (int nh = 0; nh < 4; nh++) {
                uint32_t r4[4];
                ldm4(r4, sptr(Bs + (long)(wn * 64 + nh * 16 + (lane & 15)) * PROW
                                 + c0 + (lane >> 4) * 8));
                bf[2 * nh][0]     = r4[0]; bf[2 * nh][1]     = r4[2];
                bf[2 * nh + 1][0] = r4[1]; bf[2 * nh + 1][1] = r4[3];
            }
            #pragma unroll
            for (int mt = 0; mt < 2; mt++)
                #pragma unroll
                for (int nt = 0; nt < 8; nt++)
                    mma16h(acc[mt][nt], af[mt], bf[nt]);
        }
        __syncthreads();
        buf ^= 1;
    }

    float sc[2][2] = {{1.f, 1.f}, {1.f, 1.f}};
    if (donorm) {
        #pragma unroll
        for (int mt = 0; mt < 2; mt++) {
            float sA = 0.f, sB = 0.f;
            #pragma unroll
            for (int nt = 0; nt < 8; nt++) {
                sA += acc[mt][nt][0] * acc[mt][nt][0] + acc[mt][nt][1] * acc[mt][nt][1];
                sB += acc[mt][nt][2] * acc[mt][nt][2] + acc[mt][nt][3] * acc[mt][nt][3];
            }
            #pragma unroll
            for (int o = 1; o <= 2; o <<= 1) {
                sA += __shfl_xor_sync(0xffffffffu, sA, o);
                sB += __shfl_xor_sync(0xffffffffu, sB, o);
            }
            sc[mt][0] = coef / fmaxf(sqrtf(sA), 1e-12f);
            sc[mt][1] = coef / fmaxf(sqrtf(sB), 1e-12f);
        }
    }

    __half* Cb = C + (long)blockIdx.y * 128 * CD + (long)blockIdx.x * 128;
    #pragma unroll
    for (int mt = 0; mt < 2; mt++)
        #pragma unroll
        for (int nt = 0; nt < 8; nt++) {
            long r0  = wm * 32 + mt * 16 + g;
            int  col = wn * 64 + nt * 8 + 2 * tig;
            *(__half2*)&Cb[r0 * CD + col] =
                __floats2half2_rn(acc[mt][nt][0] * sc[mt][0],
                                  acc[mt][nt][1] * sc[mt][0]);
            *(__half2*)&Cb[(r0 + 8) * CD + col] =
                __floats2half2_rn(acc[mt][nt][2] * sc[mt][1],
                                  acc[mt][nt][3] * sc[mt][1]);
        }
}

// ---------------------------------------------------------------------------
// Fused flash attention (round-15 proven structure, no occupancy cap):
// S'=Q'.K^T (fp16 MMA, all 64 scores materialized), E=2^S' -> uint8
// fragment-order gmem tile + fp16 register repack -> O += E.V, Z += rowsum.
// 256 threads = 8 warps, warp owns 16 q rows.  grid (CL/128, BHn).
// ---------------------------------------------------------------------------
__global__ __launch_bounds__(256) void flash_kernel(
    const __half* __restrict__ Qh, const __half* __restrict__ Kh,
    const __half* __restrict__ Vh, uint8_t* __restrict__ E8,
    float* __restrict__ invZ, float* __restrict__ out)
{
    __shared__ __half Qs[128][72];
    __shared__ __half Ks[64][72];
    __shared__ __half Vs[64][72];

    const int z = blockIdx.y, b = z >> 4, h = z & 15;
    const int qbase = blockIdx.x * 128;
    const int tid = threadIdx.x, w = tid >> 5, lane = tid & 31;
    const int g = lane >> 2, tig = lane & 3;

    const __half* Qg = Qh + ((long)b * CL + qbase) * CD + h * 64;
    #pragma unroll
    for (int j = 0; j < 4; j++) {
        int f = tid + 256 * j;
        int r = f >> 3, c = (f & 7) * 8;
        *(uint4*)&Qs[r][c] = *(const uint4*)(Qg + (long)r * CD + c);
    }
    __syncthreads();
    uint32_t aq[4][4];
    #pragma unroll
    for (int kc = 0; kc < 4; kc++)
        ldm4(aq[kc], sptr(&Qs[w * 16 + (lane & 15)][kc * 16 + (lane >> 4) * 8]));

    const __half* Kg = Kh + (long)b * CL * CD + h * 64;
    const __half* Vg = Vh + (long)b * CL * CD + h * 64;

    float acc_o[8][4];
    #pragma unroll
    for (int i = 0; i < 8; i++)
        #pragma unroll
        for (int r = 0; r < 4; r++) acc_o[i][r] = 0.f;
    float zr0 = 0.f, zr1 = 0.f;

    uint4 pk[2], pv[2];
    #pragma unroll
    for (int j = 0; j < 2; j++) {
        int f = tid + 256 * j;
        int r = f >> 3, c = (f & 7) * 8;
        pk[j] = *(const uint4*)(Kg + (long)r * CD + c);
        pv[j] = *(const uint4*)(Vg + (long)r * CD + c);
    }

    uint4* Etile = (uint4*)E8 + ((long)z * (CL / 128) + blockIdx.x) * TILE_U4;

    for (int kt = 0; kt < CL / 64; kt++) {
        #pragma unroll
        for (int j = 0; j < 2; j++) {
            int f = tid + 256 * j;
            int r = f >> 3, c = (f & 7) * 8;
            *(uint4*)&Ks[r][c] = pk[j];
            *(uint4*)&Vs[r][c] = pv[j];
        }
        __syncthreads();

        if (kt + 1 < CL / 64) {
            #pragma unroll
            for (int j = 0; j < 2; j++) {
                int f = tid + 256 * j;
                int r = f >> 3, c = (f & 7) * 8;
                long row = (long)((kt + 1) * 64 + r);
                pk[j] = *(const uint4*)(Kg + row * CD + c);
                pv[j] = *(const uint4*)(Vg + row * CD + c);
            }
        }

        float s[8][4];
        #pragma unroll
        for (int i = 0; i < 8; i++)
            #pragma unroll
            for (int r = 0; r < 4; r++) s[i][r] = 0.f;

        #pragma unroll
        for (int kc = 0; kc < 4; kc++) {
            #pragma unroll
            for (int p = 0; p < 4; p++) {
                uint32_t r4[4];
                ldm4(r4, sptr(&Ks[p * 16 + (lane & 15)][kc * 16 + (lane >> 4) * 8]));
                uint32_t b0[2] = {r4[0], r4[2]}, b1[2] = {r4[1], r4[3]};
                mma16h(s[2 * p],     aq[kc], b0);
                mma16h(s[2 * p + 1], aq[kc], b1);
            }
        }

        uint32_t ehlo[8], ehhi[8];
        uint32_t encLo[8], encHi[8];
        #pragma unroll
        for (int nt = 0; nt < 8; nt++) {
            float e0 = ex2(s[nt][0]);
            float e1 = ex2(s[nt][1]);
            float e2 = ex2(s[nt][2]);
            float e3 = ex2(s[nt][3]);
            __half2 lo = __floats2half2_rn(e0, e1);
            __half2 hi = __floats2half2_rn(e2, e3);
            ehlo[nt] = *(uint32_t*)&lo;
            ehhi[nt] = *(uint32_t*)&hi;
            zr0 += e0 + e1;
            zr1 += e2 + e3;
            encLo[nt] = __byte_perm(e_enc(e0), e_enc(e1), 0x0040);
            encHi[nt] = __byte_perm(e_enc(e2), e_enc(e3), 0x0040);
        }

        {
            uint4 s0, s1;
            s0.x = __byte_perm(encLo[0], encLo[1], 0x5410);
            s0.y = __byte_perm(encHi[0], encHi[1], 0x5410);
            s0.z = __byte_perm(encLo[2], encLo[3], 0x5410);
            s0.w = __byte_perm(encHi[2], encHi[3], 0x5410);
            s1.x = __byte_perm(encLo[4], encLo[5], 0x5410);
            s1.y = __byte_perm(encHi[4], encHi[5], 0x5410);
            s1.z = __byte_perm(encLo[6], encLo[7], 0x5410);
            s1.w = __byte_perm(encHi[6], encHi[7], 0x5410);
            uint4* p = Etile + (long)kt * 512 + tid;
            __stcs(p,       s0);
            __stcs(p + 256, s1);
        }

        #pragma unroll
        for (int kc = 0; kc < 4; kc++) {
            uint32_t a[4] = {ehlo[2 * kc], ehhi[2 * kc], ehlo[2 * kc + 1], ehhi[2 * kc + 1]};
            #pragma unroll
            for (int p = 0; p < 4; p++) {
                uint32_t r4[4];
                ldm4t(r4, sptr(&Vs[kc * 16 + (lane & 15)][p * 16 + (lane >> 4) * 8]));
                uint32_t b0[2] = {r4[0], r4[1]}, b1[2] = {r4[2], r4[3]};
                mma16h(acc_o[2 * p],     a, b0);
                mma16h(acc_o[2 * p + 1], a, b1);
            }
        }
        __syncthreads();
    }

    zr0 += __shfl_xor_sync(0xffffffffu, zr0, 1);
    zr0 += __shfl_xor_sync(0xffffffffu, zr0, 2);
    zr1 += __shfl_xor_sync(0xffffffffu, zr1, 1);
    zr1 += __shfl_xor_sync(0xffffffffu, zr1, 2);
    const float iz0 = 1.0f / zr0;
    const float iz1 = 1.0f / zr1;
    if (tig == 0) {
        invZ[(long)z * CL + qbase + w * 16 + g]     = iz0;
        invZ[(long)z * CL + qbase + w * 16 + g + 8] = iz1;
    }
    float* Ob = out + (long)z * CL * CDK + (long)(qbase + w * 16) * CDK;
    #pragma unroll
    for (int nt = 0; nt < 8; nt++) {
        int col = nt * 8 + 2 * tig;
        *(float2*)&Ob[(long)g * CDK + col] =
            make_float2(acc_o[nt][0] * iz0, acc_o[nt][1] * iz0);
        *(float2*)&Ob[(long)(g + 8) * CDK + col] =
            make_float2(acc_o[nt][2] * iz1, acc_o[nt][3] * iz1);
    }
}

// ---------------------------------------------------------------------------
// avg from fragment-order uint8 E (weights in smem; 2 CTA/SM):
//   avg[b,q,k] = (1/16) sum_h invZ[h,q] * (ELO + enc*ESTEP)
// grid (CL/128 ktgroups of 2, CL/128 qtiles, CB); 256 threads.
// ---------------------------------------------------------------------------
__global__ __launch_bounds__(256, 2) void avg_kernel(const uint8_t* __restrict__ E8,
                                                     const float* __restrict__ invZ,
                                                     float* __restrict__ avg)
{
    __shared__ float Wsm[128][17];

    const int b   = blockIdx.z;
    const int qt  = blockIdx.y;
    const int ktg = blockIdx.x;
    const int tid = threadIdx.x, w = tid >> 5, lane = tid & 31;
    const int g = lane >> 2, tig = lane & 3;
    const int rA = w * 16 + g;
    const int row0 = qt * 128 + rA;

    for (int i = tid; i < 128 * CH; i += 256) {
        int r = i >> 4, h = i & 15;
        Wsm[r][h] = invZ[(long)(b * CH + h) * CL + qt * 128 + r] * (1.0f / CH);
    }
    __syncthreads();

    float SW0 = 0.f, SW1 = 0.f;
    #pragma unroll
    for (int h = 0; h < CH; h++) {
        SW0 += Wsm[rA][h];
        SW1 += Wsm[rA + 8][h];
    }
    const float C0 = ELO * SW0;
    const float C1 = ELO * SW1;

    #pragma unroll
    for (int kk = 0; kk < 2; kk++) {
        const int kt = ktg * 2 + kk;
        float2 aLo[8], aHi[8];
        #pragma unroll
        for (int i = 0; i < 8; i++) {
            aLo[i] = make_float2(0.f, 0.f);
            aHi[i] = make_float2(0.f, 0.f);
        }

        #pragma unroll
        for (int h = 0; h < CH; h++) {
            const uint4* p = (const uint4*)E8
                + ((long)(b * CH + h) * (CL / 128) + qt) * TILE_U4
                + (long)kt * 512 + tid;
            const float w0 = Wsm[rA][h], w1 = Wsm[rA + 8][h];
            #pragma unroll
            for (int jj = 0; jj < 2; jj++) {
                uint4 u = __ldcs(p + jj * 256);
                const int nb = 4 * jj;
                #pragma unroll
                for (int k = 0; k < 4; k++) {
                    const int nt  = nb + (k >> 1);
                    const int nt2 = nb + 2 + (k >> 1);
                    float fx = __uint_as_float(__byte_perm(u.x, 0x4B000000u, 0x7440 + k));
                    float fy = __uint_as_float(__byte_perm(u.y, 0x4B000000u, 0x7440 + k));
                    float fz = __uint_as_float(__byte_perm(u.z, 0x4B000000u, 0x7440 + k));
                    float fw = __uint_as_float(__byte_perm(u.w, 0x4B000000u, 0x7440 + k));
                    float* dLo  = (k & 1) ? &aLo[nt].y  : &aLo[nt].x;
                    float* dHi  = (k & 1) ? &aHi[nt].y  : &aHi[nt].x;
                    float* dLo2 = (k & 1) ? &aLo[nt2].y : &aLo[nt2].x;
                    float* dHi2 = (k & 1) ? &aHi[nt2].y : &aHi[nt2].x;
                    *dLo  = fmaf(w0, fx - EMAGIC, *dLo);
                    *dHi  = fmaf(w1, fy - EMAGIC, *dHi);
                    *dLo2 = fmaf(w0, fz - EMAGIC, *dLo2);
                    *dHi2 = fmaf(w1, fw - EMAGIC, *dHi2);
                }
            }
        }

        float* A0 = avg + ((long)b * CL + row0) * CL;
        #pragma unroll
        for (int nt = 0; nt < 8; nt++) {
            int col = kt * 64 + nt * 8 + 2 * tig;
            *(float2*)&A0[col] =
                make_float2(fmaf(ESTEP, aLo[nt].x, C0), fmaf(ESTEP, aLo[nt].y, C0));
            *(float2*)&A0[8L * CL + col] =
                make_float2(fmaf(ESTEP, aHi[nt].x, C1), fmaf(ESTEP, aHi[nt].y, C1));
        }
    }
}

// ---------------------------------------------------------------------------
extern "C" void kernel_launch(void* const* d_in, const int* in_sizes, int n_in,
                              void* d_out, int out_size)
{
    const float* q  = (const float*)d_in[0];
    const float* k  = (const float*)d_in[1];
    const float* v  = (const float*)d_in[2];
    const float* wq = (const float*)d_in[3];
    const float* wk = (const float*)d_in[4];
    const float* wv = (const float*)d_in[5];

    float* out = (float*)d_out;                        // [B,H,L,64]
    float* avg = out + (long)CB * CH * CL * CDK;       // [B,L,L]

    float   *iZ;
    __half  *Xh, *Wh, *Qh, *Kh, *Vh;
    uint8_t *Ep;
    cudaGetSymbolAddress((void**)&Xh, g_Xh);
    cudaGetSymbolAddress((void**)&Wh, g_Wh);
    cudaGetSymbolAddress((void**)&Qh, g_Qh);
    cudaGetSymbolAddress((void**)&Kh, g_Kh);
    cudaGetSymbolAddress((void**)&Vh, g_Vh);
    cudaGetSymbolAddress((void**)&Ep, g_E8);
    cudaGetSymbolAddress((void**)&iZ, g_invZ);

    // allow 72KB dynamic smem for the double-buffered projection kernel
    static int smem_set = 0;
    if (!smem_set) {
        cudaFuncSetAttribute(proj_norm_kernel,
                             cudaFuncAttributeMaxDynamicSharedMemorySize,
                             PSMEM_BYTES);
        smem_set = 1;
    }

    // 0) fp32 -> fp16 conversion of all GEMM operands
    dim3 cg(PROJ_ELEMS / (256 * 8), 6);
    cvt_kernel<<<cg, 256>>>(q, k, v, wq, wk, wv, Xh, Wh);

    // 1) Projections + fused per-head L2 norm (cp.async double-buffered)
    dim3 pg(CD / 128, (CB * CL) / 128, 3);
    proj_norm_kernel<<<pg, 256, PSMEM_BYTES>>>(Xh, Wh, Qh, Kh, Vh);

    // 2) Fused attention: fragment-order uint8 E + invZ + out
    dim3 fg(CL / 128, BHn);
    flash_kernel<<<fg, 256>>>(Qh, Kh, Vh, Ep, iZ, out);

    // 3) attn_avg from fragment-order uint8 E
    dim3 ag(CL / 128, CL / 128, CB);
    avg_kernel<<<ag, 256>>>(Ep, iZ, avg);
}